// round 9
// baseline (speedup 1.0000x reference)
#include <cuda_runtime.h>
#include <math.h>
#include <stdint.h>

// ---------------- problem constants ----------------
#define BB 4
#define NN 1024
#define DIMM 1024
#define HH 16
#define DH 64
#define NUM_MEM 64
#define JJ (NN + NUM_MEM)   // 1088
#define TOPKK 64
#define SCALEF 0.125f
#define NEGMAX (-3.402823466e38f)
#define JROW 1089           // padded row stride in shared

// ---------------- device scratch (allocation-free) ----------------
__device__ float g_q  [(size_t)BB*HH*NN*DH];
__device__ float g_k  [(size_t)BB*HH*JJ*DH];
__device__ float g_v  [(size_t)BB*HH*JJ*DH];
__device__ float g_raw[(size_t)BB*HH*NN*JJ];   // raw dots -> (reused) post-mixed attn
__device__ float g_mix[(size_t)BB*HH*NN*JJ];   // pre-mixed dots (only j < jlen valid)
__device__ float g_ctx[(size_t)BB*NN*DIMM];

// monotone fp32 -> uint32 key (order-preserving)
__device__ __forceinline__ unsigned fkey(float f) {
    unsigned u = __float_as_uint(f);
    return (u & 0x80000000u) ? ~u : (u | 0x80000000u);
}

// ---------------- kernel 1: broadcast memory K/V into the kv cache ----------------
__global__ void fill_mem_kernel(const float* __restrict__ mk, const float* __restrict__ mv) {
    int idx = blockIdx.x * blockDim.x + threadIdx.x;
    if (idx >= HH * NUM_MEM * DH) return;
    int h    = idx / (NUM_MEM * DH);
    int rest = idx % (NUM_MEM * DH);
    float kv = mk[idx], vv = mv[idx];
#pragma unroll
    for (int b = 0; b < BB; b++) {
        size_t o = ((size_t)(b * HH + h) * JJ) * DH + rest;
        g_k[o] = kv;
        g_v[o] = vv;
    }
}

// ---------------- kernel 2: 128x128x16 double-buffered SGEMM, C = A @ B^T ----------------
// (verified passing in round 2: 255us/launch, rel_err 4.28e-7)
// EPI 0/1/3: scatter epilogues into g_q/g_k/g_v. EPI 2: A = g_ctx, C = out + bias.
// M=4096, N=1024, K=1024. grid = (8, 32), 256 threads.
#define LDS_PAD 132
template <int EPI>
__global__ __launch_bounds__(256)
void sgemm128(const float* __restrict__ A, const float* __restrict__ Bw,
              const float* __restrict__ bias, float* __restrict__ C) {
    constexpr int K = 1024;
    constexpr int BK = 16;
    const float* Ap = (EPI == 2) ? (const float*)g_ctx : A;

    const int bm = blockIdx.y * 128;
    const int bn = blockIdx.x * 128;

    __shared__ __align__(16) float As[2][BK][LDS_PAD];
    __shared__ __align__(16) float Bs[2][BK][LDS_PAD];

    const int tid = threadIdx.x;
    const int tx = tid & 15, ty = tid >> 4;
    const int lm = tid >> 2;            // 0..63
    const int lk = (tid & 3) << 2;      // 0,4,8,12

    const float* Ald = Ap + (size_t)(bm + lm) * K + lk;
    const float* Bld = Bw + (size_t)(bn + lm) * K + lk;
    const size_t half = (size_t)64 * K;

    float4 ra0 = *(const float4*)(Ald);
    float4 ra1 = *(const float4*)(Ald + half);
    float4 rb0 = *(const float4*)(Bld);
    float4 rb1 = *(const float4*)(Bld + half);

    float acc[8][8];
#pragma unroll
    for (int i = 0; i < 8; i++)
#pragma unroll
        for (int j = 0; j < 8; j++) acc[i][j] = 0.f;

    // prologue store into buffer 0
    As[0][lk+0][lm] = ra0.x; As[0][lk+1][lm] = ra0.y; As[0][lk+2][lm] = ra0.z; As[0][lk+3][lm] = ra0.w;
    As[0][lk+0][lm+64] = ra1.x; As[0][lk+1][lm+64] = ra1.y; As[0][lk+2][lm+64] = ra1.z; As[0][lk+3][lm+64] = ra1.w;
    Bs[0][lk+0][lm] = rb0.x; Bs[0][lk+1][lm] = rb0.y; Bs[0][lk+2][lm] = rb0.z; Bs[0][lk+3][lm] = rb0.w;
    Bs[0][lk+0][lm+64] = rb1.x; Bs[0][lk+1][lm+64] = rb1.y; Bs[0][lk+2][lm+64] = rb1.z; Bs[0][lk+3][lm+64] = rb1.w;
    __syncthreads();

    int buf = 0;
    for (int t = 1; t < K / BK; t++) {
        const float* A2 = Ald + t * BK;
        const float* B2 = Bld + t * BK;
        ra0 = *(const float4*)(A2);
        ra1 = *(const float4*)(A2 + half);
        rb0 = *(const float4*)(B2);
        rb1 = *(const float4*)(B2 + half);

#pragma unroll
        for (int kk = 0; kk < BK; kk++) {
            float a[8], b[8];
            *(float4*)(a)     = *(const float4*)&As[buf][kk][ty * 8];
            *(float4*)(a + 4) = *(const float4*)&As[buf][kk][ty * 8 + 4];
            *(float4*)(b)     = *(const float4*)&Bs[buf][kk][tx * 8];
            *(float4*)(b + 4) = *(const float4*)&Bs[buf][kk][tx * 8 + 4];
#pragma unroll
            for (int i = 0; i < 8; i++)
#pragma unroll
                for (int j = 0; j < 8; j++) acc[i][j] += a[i] * b[j];
        }

        const int nb = buf ^ 1;
        As[nb][lk+0][lm] = ra0.x; As[nb][lk+1][lm] = ra0.y; As[nb][lk+2][lm] = ra0.z; As[nb][lk+3][lm] = ra0.w;
        As[nb][lk+0][lm+64] = ra1.x; As[nb][lk+1][lm+64] = ra1.y; As[nb][lk+2][lm+64] = ra1.z; As[nb][lk+3][lm+64] = ra1.w;
        Bs[nb][lk+0][lm] = rb0.x; Bs[nb][lk+1][lm] = rb0.y; Bs[nb][lk+2][lm] = rb0.z; Bs[nb][lk+3][lm] = rb0.w;
        Bs[nb][lk+0][lm+64] = rb1.x; Bs[nb][lk+1][lm+64] = rb1.y; Bs[nb][lk+2][lm+64] = rb1.z; Bs[nb][lk+3][lm+64] = rb1.w;
        __syncthreads();
        buf = nb;
    }

    // last slice
#pragma unroll
    for (int kk = 0; kk < BK; kk++) {
        float a[8], b[8];
        *(float4*)(a)     = *(const float4*)&As[buf][kk][ty * 8];
        *(float4*)(a + 4) = *(const float4*)&As[buf][kk][ty * 8 + 4];
        *(float4*)(b)     = *(const float4*)&Bs[buf][kk][tx * 8];
        *(float4*)(b + 4) = *(const float4*)&Bs[buf][kk][tx * 8 + 4];
#pragma unroll
        for (int i = 0; i < 8; i++)
#pragma unroll
            for (int j = 0; j < 8; j++) acc[i][j] += a[i] * b[j];
    }

#pragma unroll
    for (int i = 0; i < 8; i++) {
        int m = bm + ty * 8 + i;
#pragma unroll
        for (int j = 0; j < 8; j++) {
            int n = bn + tx * 8 + j;
            if (EPI == 2) {
                C[(size_t)m * 1024 + n] = acc[i][j] + bias[n];
            } else {
                int b = m >> 10, pos = m & 1023;
                int h = n >> 6,  d   = n & 63;
                if (EPI == 0) {
                    g_q[((size_t)(b * HH + h) * NN + pos) * DH + d] = acc[i][j];
                } else if (EPI == 1) {
                    g_k[((size_t)(b * HH + h) * JJ + NUM_MEM + pos) * DH + d] = acc[i][j];
                } else {
                    g_v[((size_t)(b * HH + h) * JJ + NUM_MEM + pos) * DH + d] = acc[i][j];
                }
            }
        }
    }
}

// ---------------- kernel 3: raw dots = SCALE * Q @ K^T per (b,h), 64x64 tiles, causal skip
__global__ __launch_bounds__(256)
void dots_gemm() {
    const int bh = blockIdx.z;
    const int i0 = blockIdx.y * 64;
    const int j0 = blockIdx.x * 64;
    if (j0 > i0 + 127) return;

    const float* Qp = g_q + ((size_t)bh * NN + i0) * DH;
    const float* Kp = g_k + ((size_t)bh * JJ + j0) * DH;

    __shared__ float Qs[64][68];
    __shared__ float Ks[64][68];

    const int tid = threadIdx.x;
    for (int f = tid; f < 1024; f += 256) {
        int r = f >> 4, dq = (f & 15) << 2;
        float4 q4 = *(const float4*)(Qp + (size_t)r * DH + dq);
        Qs[dq + 0][r] = q4.x; Qs[dq + 1][r] = q4.y; Qs[dq + 2][r] = q4.z; Qs[dq + 3][r] = q4.w;
        float4 k4 = *(const float4*)(Kp + (size_t)r * DH + dq);
        Ks[dq + 0][r] = k4.x; Ks[dq + 1][r] = k4.y; Ks[dq + 2][r] = k4.z; Ks[dq + 3][r] = k4.w;
    }
    __syncthreads();

    const int tx = tid & 15, ty = tid >> 4;
    float acc[4][4];
#pragma unroll
    for (int i = 0; i < 4; i++)
#pragma unroll
        for (int j = 0; j < 4; j++) acc[i][j] = 0.f;

#pragma unroll 8
    for (int d = 0; d < 64; d++) {
        float a[4], b[4];
#pragma unroll
        for (int i = 0; i < 4; i++) a[i] = Qs[d][ty * 4 + i];
#pragma unroll
        for (int j = 0; j < 4; j++) b[j] = Ks[d][tx * 4 + j];
#pragma unroll
        for (int i = 0; i < 4; i++)
#pragma unroll
            for (int j = 0; j < 4; j++) acc[i][j] += a[i] * b[j];
    }

    size_t ob = ((size_t)bh * NN + i0 + ty * 4) * JJ + j0 + tx * 4;
#pragma unroll
    for (int i = 0; i < 4; i++)
#pragma unroll
        for (int j = 0; j < 4; j++)
            g_raw[ob + (size_t)i * JJ + j] = acc[i][j] * SCALEF;
}

// ---------------- kernel 4: pre-softmax talking heads (masked region never written:
// topk only reads j < jlen, so the NEGMAX stores were dead traffic) ----------------
__global__ __launch_bounds__(256)
void premix_kernel(const float* __restrict__ pre_proj) {
    const int b = blockIdx.x >> 10;
    const int i = blockIdx.x & 1023;
    __shared__ float pp[256];
    if (threadIdx.x < 256) pp[threadIdx.x] = pre_proj[threadIdx.x];
    __syncthreads();

    const int jlen = i + NUM_MEM + 1;             // valid kv count
    const size_t base = ((size_t)b * HH * NN + i) * JJ;
    const size_t hs = (size_t)NN * JJ;

    for (int j = threadIdx.x; j < jlen; j += 256) {
        float r[HH];
#pragma unroll
        for (int h = 0; h < HH; h++) r[h] = g_raw[base + (size_t)h * hs + j];
#pragma unroll
        for (int kk = 0; kk < HH; kk++) {
            float s = 0.f;
#pragma unroll
            for (int h = 0; h < HH; h++) s += r[h] * pp[h * HH + kk];
            g_mix[base + (size_t)kk * hs + j] = s;
        }
    }
}

// ---------------- kernel 5: exact top-k (radix select) + softmax + post-mix ----------------
__global__ __launch_bounds__(512)
void topk_kernel(const float* __restrict__ post_proj) {
    extern __shared__ float sm[];
    float* rows = sm;                                  // 16 * JROW floats
    unsigned* hist = (unsigned*)(sm + HH * JROW);      // 16 * 256 uints
    __shared__ float s_post[256];

    const int b = blockIdx.x >> 10;
    const int i = blockIdx.x & 1023;
    const int tid = threadIdx.x;
    const int w = tid >> 5, lane = tid & 31;
    if (tid < 256) s_post[tid] = post_proj[tid];

    const int jlen = i + NUM_MEM + 1;
    float* srow = rows + w * JROW;
    unsigned* myh = hist + w * 256;
    const size_t base = ((size_t)(b * HH + w) * NN + i) * JJ;

    float m = NEGMAX;
    for (int j = lane; j < jlen; j += 32) {
        float v = g_mix[base + j];
        srow[j] = v;
        m = fmaxf(m, v);
    }
#pragma unroll
    for (int o = 16; o; o >>= 1) m = fmaxf(m, __shfl_xor_sync(0xffffffffu, m, o));

    unsigned prefix = 0;
    int r = TOPKK;
#pragma unroll
    for (int shift = 24; shift >= 0; shift -= 8) {
        for (int t = lane; t < 256; t += 32) myh[t] = 0;
        __syncwarp();
        unsigned pm = (shift == 24) ? 0u : (0xFFFFFFFFu << (shift + 8));
        for (int j = lane; j < jlen; j += 32) {
            unsigned kx = fkey(srow[j]);
            if ((kx & pm) == prefix) atomicAdd(&myh[(kx >> shift) & 255u], 1u);
        }
        __syncwarp();
        unsigned tot = 0;
#pragma unroll
        for (int t = 0; t < 8; t++) tot += myh[lane * 8 + t];
        unsigned s = tot;
#pragma unroll
        for (int o = 1; o < 32; o <<= 1) {
            unsigned tt = __shfl_down_sync(0xffffffffu, s, o);
            if (lane + o < 32) s += tt;
        }
        unsigned s_strict = s - tot;
        bool sel = ((unsigned)r > s_strict) && ((unsigned)r <= s);
        unsigned bal = __ballot_sync(0xffffffffu, sel);
        int sl = __ffs(bal) - 1;
        unsigned pick = 0; int newr = r;
        if (sel) {
            int rr = r - (int)s_strict;
#pragma unroll
            for (int t = 7; t >= 0; t--) {
                unsigned c = myh[lane * 8 + t];
                if (rr <= (int)c) { pick = (unsigned)(lane * 8 + t); newr = rr; break; }
                rr -= (int)c;
            }
        }
        pick = __shfl_sync(0xffffffffu, pick, sl);
        r    = __shfl_sync(0xffffffffu, newr, sl);
        prefix |= pick << shift;
    }

    float sum = 0.f;
    for (int j = lane; j < JJ; j += 32) {
        float e = 0.f;
        if (j < jlen) {
            float v = srow[j];
            if (fkey(v) >= prefix) e = expf(v - m);
        }
        srow[j] = e;
        sum += e;
    }
#pragma unroll
    for (int o = 16; o; o >>= 1) sum += __shfl_xor_sync(0xffffffffu, sum, o);
    float inv = 1.0f / sum;
    for (int j = lane; j < JJ; j += 32) srow[j] *= inv;

    __syncthreads();

    const size_t ob = ((size_t)(b * HH) * NN + i) * JJ;
    const size_t hs = (size_t)NN * JJ;
    for (int j = tid; j < JJ; j += 512) {
        float a[HH];
#pragma unroll
        for (int hh = 0; hh < HH; hh++) a[hh] = rows[hh * JROW + j];
#pragma unroll
        for (int kk = 0; kk < HH; kk++) {
            float sacc = 0.f;
#pragma unroll
            for (int hh = 0; hh < HH; hh++) sacc += a[hh] * s_post[hh * 16 + kk];
            g_raw[ob + (size_t)kk * hs + j] = sacc;
        }
    }
}

// ---------------- kernel 6: context = attn2 @ V per (b,h), causal-bounded, pipelined ----
__global__ __launch_bounds__(256)
void av_gemm() {
    const int bh = blockIdx.z;
    const int b = bh >> 4, h = bh & 15;
    const int i0 = blockIdx.y * 64;

    const float* Ap = g_raw + ((size_t)bh * NN + i0) * JJ;
    const float* Vp = g_v + (size_t)bh * JJ * DH;
    const int kmax = min(JJ, i0 + 128);

    __shared__ float As[16][68];
    __shared__ float Bs[16][64];

    const int tid = threadIdx.x;
    const int tx = tid & 15, ty = tid >> 4;
    const int ar = tid >> 2, akq = (tid & 3) << 2;
    const int br = tid >> 4, bdq = (tid & 15) << 2;

    float acc[4][4];
#pragma unroll
    for (int i = 0; i < 4; i++)
#pragma unroll
        for (int j = 0; j < 4; j++) acc[i][j] = 0.f;

    // prefetch first slice
    float4 a4 = *(const float4*)(Ap + (size_t)ar * JJ + akq);
    float4 b4 = *(const float4*)(Vp + (size_t)br * DH + bdq);

    for (int kt = 0; kt < kmax; kt += 16) {
        __syncthreads();
        As[akq + 0][ar] = a4.x; As[akq + 1][ar] = a4.y; As[akq + 2][ar] = a4.z; As[akq + 3][ar] = a4.w;
        *(float4*)&Bs[br][bdq] = b4;
        __syncthreads();

        // issue next slice's loads while computing this one
        if (kt + 16 < kmax) {
            a4 = *(const float4*)(Ap + (size_t)ar * JJ + kt + 16 + akq);
            b4 = *(const float4*)(Vp + (size_t)(kt + 16 + br) * DH + bdq);
        }

#pragma unroll
        for (int kk = 0; kk < 16; kk++) {
            float a[4], bb[4];
#pragma unroll
            for (int i = 0; i < 4; i++) a[i] = As[kk][ty * 4 + i];
#pragma unroll
            for (int j = 0; j < 4; j++) bb[j] = Bs[kk][tx * 4 + j];
#pragma unroll
            for (int i = 0; i < 4; i++)
#pragma unroll
                for (int j = 0; j < 4; j++) acc[i][j] += a[i] * bb[j];
        }
    }

    const int irow = i0 + ty * 4;
    const int d0 = h * DH + tx * 4;
#pragma unroll
    for (int i = 0; i < 4; i++)
#pragma unroll
        for (int j = 0; j < 4; j++)
            g_ctx[((size_t)b * NN + irow + i) * DIMM + d0 + j] = acc[i][j];
}

// ---------------- host launcher ----------------
extern "C" void kernel_launch(void* const* d_in, const int* in_sizes, int n_in,
                              void* d_out, int out_size) {
    const float* x        = (const float*)d_in[0];
    const float* Wq       = (const float*)d_in[1];
    const float* Wk       = (const float*)d_in[2];
    const float* Wv       = (const float*)d_in[3];
    const float* pre_proj = (const float*)d_in[4];
    const float* post_proj= (const float*)d_in[5];
    const float* mem_k    = (const float*)d_in[6];
    const float* mem_v    = (const float*)d_in[7];
    const float* Wout     = (const float*)d_in[8];
    const float* bout     = (const float*)d_in[9];
    float* out = (float*)d_out;
    (void)in_sizes; (void)n_in; (void)out_size;

    const int topk_smem = (HH * JROW + HH * 256) * 4;  // 86,080 bytes
    cudaFuncSetAttribute(topk_kernel, cudaFuncAttributeMaxDynamicSharedMemorySize, topk_smem);

    fill_mem_kernel<<<64, 1024>>>(mem_k, mem_v);

    sgemm128<0><<<dim3(8, 32), 256>>>(x, Wq, nullptr, nullptr);
    sgemm128<1><<<dim3(8, 32), 256>>>(x, Wk, nullptr, nullptr);
    sgemm128<3><<<dim3(8, 32), 256>>>(x, Wv, nullptr, nullptr);

    dots_gemm<<<dim3(17, 16, 64), 256>>>();

    premix_kernel<<<BB * NN, 256>>>(pre_proj);

    topk_kernel<<<BB * NN, 512, topk_smem>>>(post_proj);

    av_gemm<<<dim3(1, 16, 64), 256>>>();

    sgemm128<2><<<dim3(8, 32), 256>>>(nullptr, Wout, bout, out);
}

// round 10
// speedup vs baseline: 1.2318x; 1.2318x over previous
#include <cuda_runtime.h>
#include <math.h>
#include <stdint.h>

// ---------------- problem constants ----------------
#define BB 4
#define NN 1024
#define DIMM 1024
#define HH 16
#define DH 64
#define NUM_MEM 64
#define JJ (NN + NUM_MEM)   // 1088
#define TOPKK 64
#define SCALEF 0.125f
#define NEGMAX (-3.402823466e38f)
#define JROW 1089           // padded row stride in shared

// ---------------- device scratch (allocation-free) ----------------
__device__ float g_q  [(size_t)BB*HH*NN*DH];
__device__ float g_k  [(size_t)BB*HH*JJ*DH];
__device__ float g_v  [(size_t)BB*HH*JJ*DH];
__device__ float g_raw[(size_t)BB*HH*NN*JJ];   // raw dots -> (reused) post-mixed attn
__device__ float g_mix[(size_t)BB*HH*NN*JJ];   // pre-mixed dots (only j < jlen valid)
__device__ float g_ctx[(size_t)BB*NN*DIMM];

// monotone fp32 -> uint32 key (order-preserving)
__device__ __forceinline__ unsigned fkey(float f) {
    unsigned u = __float_as_uint(f);
    return (u & 0x80000000u) ? ~u : (u | 0x80000000u);
}

// ---------------- kernel 1: broadcast memory K/V into the kv cache ----------------
__global__ void fill_mem_kernel(const float* __restrict__ mk, const float* __restrict__ mv) {
    int idx = blockIdx.x * blockDim.x + threadIdx.x;
    if (idx >= HH * NUM_MEM * DH) return;
    int h    = idx / (NUM_MEM * DH);
    int rest = idx % (NUM_MEM * DH);
    float kv = mk[idx], vv = mv[idx];
#pragma unroll
    for (int b = 0; b < BB; b++) {
        size_t o = ((size_t)(b * HH + h) * JJ) * DH + rest;
        g_k[o] = kv;
        g_v[o] = vv;
    }
}

// ---------------- kernel 2: 128x128x16 double-buffered SGEMM, C = A @ B^T ----------------
// __launch_bounds__(256,2): cap regs at 128 -> 2 blocks/SM -> grid 256 fits in ONE wave
// (296 slots on 148 SMs) and 16 warps/SM hide LDS/global latency.
// EPI 0/1/3: scatter epilogues into g_q/g_k/g_v. EPI 2: A = g_ctx, C = out + bias.
#define LDS_PAD 132
template <int EPI>
__global__ __launch_bounds__(256, 2)
void sgemm128(const float* __restrict__ A, const float* __restrict__ Bw,
              const float* __restrict__ bias, float* __restrict__ C) {
    constexpr int K = 1024;
    constexpr int BK = 16;
    const float* Ap = (EPI == 2) ? (const float*)g_ctx : A;

    const int bm = blockIdx.y * 128;
    const int bn = blockIdx.x * 128;

    __shared__ __align__(16) float As[2][BK][LDS_PAD];
    __shared__ __align__(16) float Bs[2][BK][LDS_PAD];

    const int tid = threadIdx.x;
    const int tx = tid & 15, ty = tid >> 4;
    const int lm = tid >> 2;            // 0..63
    const int lk = (tid & 3) << 2;      // 0,4,8,12

    const float* Ald = Ap + (size_t)(bm + lm) * K + lk;
    const float* Bld = Bw + (size_t)(bn + lm) * K + lk;
    const size_t half = (size_t)64 * K;

    float4 ra0 = *(const float4*)(Ald);
    float4 ra1 = *(const float4*)(Ald + half);
    float4 rb0 = *(const float4*)(Bld);
    float4 rb1 = *(const float4*)(Bld + half);

    float acc[8][8];
#pragma unroll
    for (int i = 0; i < 8; i++)
#pragma unroll
        for (int j = 0; j < 8; j++) acc[i][j] = 0.f;

    // prologue store into buffer 0
    As[0][lk+0][lm] = ra0.x; As[0][lk+1][lm] = ra0.y; As[0][lk+2][lm] = ra0.z; As[0][lk+3][lm] = ra0.w;
    As[0][lk+0][lm+64] = ra1.x; As[0][lk+1][lm+64] = ra1.y; As[0][lk+2][lm+64] = ra1.z; As[0][lk+3][lm+64] = ra1.w;
    Bs[0][lk+0][lm] = rb0.x; Bs[0][lk+1][lm] = rb0.y; Bs[0][lk+2][lm] = rb0.z; Bs[0][lk+3][lm] = rb0.w;
    Bs[0][lk+0][lm+64] = rb1.x; Bs[0][lk+1][lm+64] = rb1.y; Bs[0][lk+2][lm+64] = rb1.z; Bs[0][lk+3][lm+64] = rb1.w;
    __syncthreads();

    int buf = 0;
    for (int t = 1; t < K / BK; t++) {
        const float* A2 = Ald + t * BK;
        const float* B2 = Bld + t * BK;
        ra0 = *(const float4*)(A2);
        ra1 = *(const float4*)(A2 + half);
        rb0 = *(const float4*)(B2);
        rb1 = *(const float4*)(B2 + half);

#pragma unroll
        for (int kk = 0; kk < BK; kk++) {
            float a[8], b[8];
            *(float4*)(a)     = *(const float4*)&As[buf][kk][ty * 8];
            *(float4*)(a + 4) = *(const float4*)&As[buf][kk][ty * 8 + 4];
            *(float4*)(b)     = *(const float4*)&Bs[buf][kk][tx * 8];
            *(float4*)(b + 4) = *(const float4*)&Bs[buf][kk][tx * 8 + 4];
#pragma unroll
            for (int i = 0; i < 8; i++)
#pragma unroll
                for (int j = 0; j < 8; j++) acc[i][j] += a[i] * b[j];
        }

        const int nb = buf ^ 1;
        As[nb][lk+0][lm] = ra0.x; As[nb][lk+1][lm] = ra0.y; As[nb][lk+2][lm] = ra0.z; As[nb][lk+3][lm] = ra0.w;
        As[nb][lk+0][lm+64] = ra1.x; As[nb][lk+1][lm+64] = ra1.y; As[nb][lk+2][lm+64] = ra1.z; As[nb][lk+3][lm+64] = ra1.w;
        Bs[nb][lk+0][lm] = rb0.x; Bs[nb][lk+1][lm] = rb0.y; Bs[nb][lk+2][lm] = rb0.z; Bs[nb][lk+3][lm] = rb0.w;
        Bs[nb][lk+0][lm+64] = rb1.x; Bs[nb][lk+1][lm+64] = rb1.y; Bs[nb][lk+2][lm+64] = rb1.z; Bs[nb][lk+3][lm+64] = rb1.w;
        __syncthreads();
        buf = nb;
    }

    // last slice
#pragma unroll
    for (int kk = 0; kk < BK; kk++) {
        float a[8], b[8];
        *(float4*)(a)     = *(const float4*)&As[buf][kk][ty * 8];
        *(float4*)(a + 4) = *(const float4*)&As[buf][kk][ty * 8 + 4];
        *(float4*)(b)     = *(const float4*)&Bs[buf][kk][tx * 8];
        *(float4*)(b + 4) = *(const float4*)&Bs[buf][kk][tx * 8 + 4];
#pragma unroll
        for (int i = 0; i < 8; i++)
#pragma unroll
            for (int j = 0; j < 8; j++) acc[i][j] += a[i] * b[j];
    }

#pragma unroll
    for (int i = 0; i < 8; i++) {
        int m = bm + ty * 8 + i;
#pragma unroll
        for (int j = 0; j < 8; j++) {
            int n = bn + tx * 8 + j;
            if (EPI == 2) {
                C[(size_t)m * 1024 + n] = acc[i][j] + bias[n];
            } else {
                int b = m >> 10, pos = m & 1023;
                int h = n >> 6,  d   = n & 63;
                if (EPI == 0) {
                    g_q[((size_t)(b * HH + h) * NN + pos) * DH + d] = acc[i][j];
                } else if (EPI == 1) {
                    g_k[((size_t)(b * HH + h) * JJ + NUM_MEM + pos) * DH + d] = acc[i][j];
                } else {
                    g_v[((size_t)(b * HH + h) * JJ + NUM_MEM + pos) * DH + d] = acc[i][j];
                }
            }
        }
    }
}

// ---------------- kernel 3: raw dots = SCALE * Q @ K^T per (b,h), 64x64 tiles, causal skip
__global__ __launch_bounds__(256)
void dots_gemm() {
    const int bh = blockIdx.z;
    const int i0 = blockIdx.y * 64;
    const int j0 = blockIdx.x * 64;
    if (j0 > i0 + 127) return;

    const float* Qp = g_q + ((size_t)bh * NN + i0) * DH;
    const float* Kp = g_k + ((size_t)bh * JJ + j0) * DH;

    __shared__ float Qs[64][68];
    __shared__ float Ks[64][68];

    const int tid = threadIdx.x;
    for (int f = tid; f < 1024; f += 256) {
        int r = f >> 4, dq = (f & 15) << 2;
        float4 q4 = *(const float4*)(Qp + (size_t)r * DH + dq);
        Qs[dq + 0][r] = q4.x; Qs[dq + 1][r] = q4.y; Qs[dq + 2][r] = q4.z; Qs[dq + 3][r] = q4.w;
        float4 k4 = *(const float4*)(Kp + (size_t)r * DH + dq);
        Ks[dq + 0][r] = k4.x; Ks[dq + 1][r] = k4.y; Ks[dq + 2][r] = k4.z; Ks[dq + 3][r] = k4.w;
    }
    __syncthreads();

    const int tx = tid & 15, ty = tid >> 4;
    float acc[4][4];
#pragma unroll
    for (int i = 0; i < 4; i++)
#pragma unroll
        for (int j = 0; j < 4; j++) acc[i][j] = 0.f;

#pragma unroll 8
    for (int d = 0; d < 64; d++) {
        float a[4], b[4];
#pragma unroll
        for (int i = 0; i < 4; i++) a[i] = Qs[d][ty * 4 + i];
#pragma unroll
        for (int j = 0; j < 4; j++) b[j] = Ks[d][tx * 4 + j];
#pragma unroll
        for (int i = 0; i < 4; i++)
#pragma unroll
            for (int j = 0; j < 4; j++) acc[i][j] += a[i] * b[j];
    }

    size_t ob = ((size_t)bh * NN + i0 + ty * 4) * JJ + j0 + tx * 4;
#pragma unroll
    for (int i = 0; i < 4; i++)
#pragma unroll
        for (int j = 0; j < 4; j++)
            g_raw[ob + (size_t)i * JJ + j] = acc[i][j] * SCALEF;
}

// ---------------- kernel 4: pre-softmax talking heads (valid j range only) ----------------
__global__ __launch_bounds__(256)
void premix_kernel(const float* __restrict__ pre_proj) {
    const int b = blockIdx.x >> 10;
    const int i = blockIdx.x & 1023;
    __shared__ float pp[256];
    if (threadIdx.x < 256) pp[threadIdx.x] = pre_proj[threadIdx.x];
    __syncthreads();

    const int jlen = i + NUM_MEM + 1;             // valid kv count
    const size_t base = ((size_t)b * HH * NN + i) * JJ;
    const size_t hs = (size_t)NN * JJ;

    for (int j = threadIdx.x; j < jlen; j += 256) {
        float r[HH];
#pragma unroll
        for (int h = 0; h < HH; h++) r[h] = g_raw[base + (size_t)h * hs + j];
#pragma unroll
        for (int kk = 0; kk < HH; kk++) {
            float s = 0.f;
#pragma unroll
            for (int h = 0; h < HH; h++) s += r[h] * pp[h * HH + kk];
            g_mix[base + (size_t)kk * hs + j] = s;
        }
    }
}

// ---------------- kernel 5: exact top-k (radix select) + softmax + post-mix ----------------
// launch_bounds(512,2): 86KB smem x2 = 172KB/SM fits; 2 blocks/SM doubles latency hiding.
__global__ __launch_bounds__(512, 2)
void topk_kernel(const float* __restrict__ post_proj) {
    extern __shared__ float sm[];
    float* rows = sm;                                  // 16 * JROW floats
    unsigned* hist = (unsigned*)(sm + HH * JROW);      // 16 * 256 uints
    __shared__ float s_post[256];

    const int b = blockIdx.x >> 10;
    const int i = blockIdx.x & 1023;
    const int tid = threadIdx.x;
    const int w = tid >> 5, lane = tid & 31;
    if (tid < 256) s_post[tid] = post_proj[tid];

    const int jlen = i + NUM_MEM + 1;
    float* srow = rows + w * JROW;
    unsigned* myh = hist + w * 256;
    const size_t base = ((size_t)(b * HH + w) * NN + i) * JJ;

    float m = NEGMAX;
    for (int j = lane; j < jlen; j += 32) {
        float v = g_mix[base + j];
        srow[j] = v;
        m = fmaxf(m, v);
    }
#pragma unroll
    for (int o = 16; o; o >>= 1) m = fmaxf(m, __shfl_xor_sync(0xffffffffu, m, o));

    unsigned prefix = 0;
    int r = TOPKK;
#pragma unroll
    for (int shift = 24; shift >= 0; shift -= 8) {
        for (int t = lane; t < 256; t += 32) myh[t] = 0;
        __syncwarp();
        unsigned pm = (shift == 24) ? 0u : (0xFFFFFFFFu << (shift + 8));
        for (int j = lane; j < jlen; j += 32) {
            unsigned kx = fkey(srow[j]);
            if ((kx & pm) == prefix) atomicAdd(&myh[(kx >> shift) & 255u], 1u);
        }
        __syncwarp();
        unsigned tot = 0;
#pragma unroll
        for (int t = 0; t < 8; t++) tot += myh[lane * 8 + t];
        unsigned s = tot;
#pragma unroll
        for (int o = 1; o < 32; o <<= 1) {
            unsigned tt = __shfl_down_sync(0xffffffffu, s, o);
            if (lane + o < 32) s += tt;
        }
        unsigned s_strict = s - tot;
        bool sel = ((unsigned)r > s_strict) && ((unsigned)r <= s);
        unsigned bal = __ballot_sync(0xffffffffu, sel);
        int sl = __ffs(bal) - 1;
        unsigned pick = 0; int newr = r;
        if (sel) {
            int rr = r - (int)s_strict;
#pragma unroll
            for (int t = 7; t >= 0; t--) {
                unsigned c = myh[lane * 8 + t];
                if (rr <= (int)c) { pick = (unsigned)(lane * 8 + t); newr = rr; break; }
                rr -= (int)c;
            }
        }
        pick = __shfl_sync(0xffffffffu, pick, sl);
        r    = __shfl_sync(0xffffffffu, newr, sl);
        prefix |= pick << shift;
    }

    float sum = 0.f;
    for (int j = lane; j < JJ; j += 32) {
        float e = 0.f;
        if (j < jlen) {
            float v = srow[j];
            if (fkey(v) >= prefix) e = expf(v - m);
        }
        srow[j] = e;
        sum += e;
    }
#pragma unroll
    for (int o = 16; o; o >>= 1) sum += __shfl_xor_sync(0xffffffffu, sum, o);
    float inv = 1.0f / sum;
    for (int j = lane; j < JJ; j += 32) srow[j] *= inv;

    __syncthreads();

    // Phase C: post-mix. av_gemm only reads k < min(JJ, (i/64)*64 + 128) for this row's
    // tile, so writes beyond that bound are dead (they were zeros). Entries in
    // [jlen, bound) are still written (as zeros) — output bit-identical.
    const int wlim = min(JJ, (i & ~63) + 128);
    const size_t ob = ((size_t)(b * HH) * NN + i) * JJ;
    const size_t hs = (size_t)NN * JJ;
    for (int j = tid; j < wlim; j += 512) {
        float a[HH];
#pragma unroll
        for (int hh = 0; hh < HH; hh++) a[hh] = rows[hh * JROW + j];
#pragma unroll
        for (int kk = 0; kk < HH; kk++) {
            float sacc = 0.f;
#pragma unroll
            for (int hh = 0; hh < HH; hh++) sacc += a[hh] * s_post[hh * 16 + kk];
            g_raw[ob + (size_t)kk * hs + j] = sacc;
        }
    }
}

// ---------------- kernel 6: context = attn2 @ V per (b,h), causal-bounded, pipelined ----
__global__ __launch_bounds__(256)
void av_gemm() {
    const int bh = blockIdx.z;
    const int b = bh >> 4, h = bh & 15;
    const int i0 = blockIdx.y * 64;

    const float* Ap = g_raw + ((size_t)bh * NN + i0) * JJ;
    const float* Vp = g_v + (size_t)bh * JJ * DH;
    const int kmax = min(JJ, i0 + 128);

    __shared__ float As[16][68];
    __shared__ float Bs[16][64];

    const int tid = threadIdx.x;
    const int tx = tid & 15, ty = tid >> 4;
    const int ar = tid >> 2, akq = (tid & 3) << 2;
    const int br = tid >> 4, bdq = (tid & 15) << 2;

    float acc[4][4];
#pragma unroll
    for (int i = 0; i < 4; i++)
#pragma unroll
        for (int j = 0; j < 4; j++) acc[i][j] = 0.f;

    // prefetch first slice
    float4 a4 = *(const float4*)(Ap + (size_t)ar * JJ + akq);
    float4 b4 = *(const float4*)(Vp + (size_t)br * DH + bdq);

    for (int kt = 0; kt < kmax; kt += 16) {
        __syncthreads();
        As[akq + 0][ar] = a4.x; As[akq + 1][ar] = a4.y; As[akq + 2][ar] = a4.z; As[akq + 3][ar] = a4.w;
        *(float4*)&Bs[br][bdq] = b4;
        __syncthreads();

        // issue next slice's loads while computing this one
        if (kt + 16 < kmax) {
            a4 = *(const float4*)(Ap + (size_t)ar * JJ + kt + 16 + akq);
            b4 = *(const float4*)(Vp + (size_t)(kt + 16 + br) * DH + bdq);
        }

#pragma unroll
        for (int kk = 0; kk < 16; kk++) {
            float a[4], bb[4];
#pragma unroll
            for (int i = 0; i < 4; i++) a[i] = As[kk][ty * 4 + i];
#pragma unroll
            for (int j = 0; j < 4; j++) bb[j] = Bs[kk][tx * 4 + j];
#pragma unroll
            for (int i = 0; i < 4; i++)
#pragma unroll
                for (int j = 0; j < 4; j++) acc[i][j] += a[i] * bb[j];
        }
    }

    const int irow = i0 + ty * 4;
    const int d0 = h * DH + tx * 4;
#pragma unroll
    for (int i = 0; i < 4; i++)
#pragma unroll
        for (int j = 0; j < 4; j++)
            g_ctx[((size_t)b * NN + irow + i) * DIMM + d0 + j] = acc[i][j];
}

// ---------------- host launcher ----------------
extern "C" void kernel_launch(void* const* d_in, const int* in_sizes, int n_in,
                              void* d_out, int out_size) {
    const float* x        = (const float*)d_in[0];
    const float* Wq       = (const float*)d_in[1];
    const float* Wk       = (const float*)d_in[2];
    const float* Wv       = (const float*)d_in[3];
    const float* pre_proj = (const float*)d_in[4];
    const float* post_proj= (const float*)d_in[5];
    const float* mem_k    = (const float*)d_in[6];
    const float* mem_v    = (const float*)d_in[7];
    const float* Wout     = (const float*)d_in[8];
    const float* bout     = (const float*)d_in[9];
    float* out = (float*)d_out;
    (void)in_sizes; (void)n_in; (void)out_size;

    const int topk_smem = (HH * JROW + HH * 256) * 4;  // 86,080 bytes
    cudaFuncSetAttribute(topk_kernel, cudaFuncAttributeMaxDynamicSharedMemorySize, topk_smem);

    fill_mem_kernel<<<64, 1024>>>(mem_k, mem_v);

    sgemm128<0><<<dim3(8, 32), 256>>>(x, Wq, nullptr, nullptr);
    sgemm128<1><<<dim3(8, 32), 256>>>(x, Wk, nullptr, nullptr);
    sgemm128<3><<<dim3(8, 32), 256>>>(x, Wv, nullptr, nullptr);

    dots_gemm<<<dim3(17, 16, 64), 256>>>();

    premix_kernel<<<BB * NN, 256>>>(pre_proj);

    topk_kernel<<<BB * NN, 512, topk_smem>>>(post_proj);

    av_gemm<<<dim3(1, 16, 64), 256>>>();

    sgemm128<2><<<dim3(8, 32), 256>>>(nullptr, Wout, bout, out);
}

// round 12
// speedup vs baseline: 1.2511x; 1.0157x over previous
#include <cuda_runtime.h>
#include <math.h>
#include <stdint.h>

// ---------------- problem constants ----------------
#define BB 4
#define NN 1024
#define DIMM 1024
#define HH 16
#define DH 64
#define NUM_MEM 64
#define JJ (NN + NUM_MEM)   // 1088
#define TOPKK 64
#define SCALEF 0.125f
#define NEGMAX (-3.402823466e38f)
#define JROW 1089           // padded row stride in shared

// ---------------- device scratch (allocation-free) ----------------
__device__ float g_q  [(size_t)BB*HH*NN*DH];
__device__ float g_k  [(size_t)BB*HH*JJ*DH];
__device__ float g_v  [(size_t)BB*HH*JJ*DH];
__device__ float g_raw[(size_t)BB*HH*NN*JJ];   // raw dots -> (reused) post-mixed attn
__device__ float g_mix[(size_t)BB*HH*NN*JJ];   // pre-mixed dots (only j < jlen valid)
__device__ float g_ctx[(size_t)BB*NN*DIMM];

// monotone fp32 -> uint32 key (order-preserving)
__device__ __forceinline__ unsigned fkey(float f) {
    unsigned u = __float_as_uint(f);
    return (u & 0x80000000u) ? ~u : (u | 0x80000000u);
}

// ---------------- kernel 1: broadcast memory K/V into the kv cache ----------------
__global__ void fill_mem_kernel(const float* __restrict__ mk, const float* __restrict__ mv) {
    int idx = blockIdx.x * blockDim.x + threadIdx.x;
    if (idx >= HH * NUM_MEM * DH) return;
    int h    = idx / (NUM_MEM * DH);
    int rest = idx % (NUM_MEM * DH);
    float kv = mk[idx], vv = mv[idx];
#pragma unroll
    for (int b = 0; b < BB; b++) {
        size_t o = ((size_t)(b * HH + h) * JJ) * DH + rest;
        g_k[o] = kv;
        g_v[o] = vv;
    }
}

#define LDS_PAD 132

// ---------------- kernel 2a: MERGED QKV projection GEMM ----------------
// One launch, grid (24, 32): block column selects Wq/Wk/Wv. 768 blocks = 2.6 waves.
__global__ __launch_bounds__(256, 2)
void qkv_gemm(const float* __restrict__ x, const float* __restrict__ Wq,
              const float* __restrict__ Wk, const float* __restrict__ Wv) {
    constexpr int K = 1024;
    constexpr int BK = 16;

    const int bn3 = blockIdx.x * 128;          // 0..2944
    const int which = bn3 >> 10;               // 0=q, 1=k, 2=v
    const int bn = bn3 & 1023;                 // column within the selected matrix
    const float* Bw = (which == 0) ? Wq : (which == 1) ? Wk : Wv;
    const int bm = blockIdx.y * 128;

    __shared__ __align__(16) float As[2][BK][LDS_PAD];
    __shared__ __align__(16) float Bs[2][BK][LDS_PAD];

    const int tid = threadIdx.x;
    const int tx = tid & 15, ty = tid >> 4;
    const int lm = tid >> 2;
    const int lk = (tid & 3) << 2;

    const float* Ald = x + (size_t)(bm + lm) * K + lk;
    const float* Bld = Bw + (size_t)(bn + lm) * K + lk;
    const size_t half = (size_t)64 * K;

    float4 ra0 = *(const float4*)(Ald);
    float4 ra1 = *(const float4*)(Ald + half);
    float4 rb0 = *(const float4*)(Bld);
    float4 rb1 = *(const float4*)(Bld + half);

    float acc[8][8];
#pragma unroll
    for (int i = 0; i < 8; i++)
#pragma unroll
        for (int j = 0; j < 8; j++) acc[i][j] = 0.f;

    As[0][lk+0][lm] = ra0.x; As[0][lk+1][lm] = ra0.y; As[0][lk+2][lm] = ra0.z; As[0][lk+3][lm] = ra0.w;
    As[0][lk+0][lm+64] = ra1.x; As[0][lk+1][lm+64] = ra1.y; As[0][lk+2][lm+64] = ra1.z; As[0][lk+3][lm+64] = ra1.w;
    Bs[0][lk+0][lm] = rb0.x; Bs[0][lk+1][lm] = rb0.y; Bs[0][lk+2][lm] = rb0.z; Bs[0][lk+3][lm] = rb0.w;
    Bs[0][lk+0][lm+64] = rb1.x; Bs[0][lk+1][lm+64] = rb1.y; Bs[0][lk+2][lm+64] = rb1.z; Bs[0][lk+3][lm+64] = rb1.w;
    __syncthreads();

    int buf = 0;
    for (int t = 1; t < K / BK; t++) {
        const float* A2 = Ald + t * BK;
        const float* B2 = Bld + t * BK;
        ra0 = *(const float4*)(A2);
        ra1 = *(const float4*)(A2 + half);
        rb0 = *(const float4*)(B2);
        rb1 = *(const float4*)(B2 + half);

#pragma unroll
        for (int kk = 0; kk < BK; kk++) {
            float a[8], b[8];
            *(float4*)(a)     = *(const float4*)&As[buf][kk][ty * 8];
            *(float4*)(a + 4) = *(const float4*)&As[buf][kk][ty * 8 + 4];
            *(float4*)(b)     = *(const float4*)&Bs[buf][kk][tx * 8];
            *(float4*)(b + 4) = *(const float4*)&Bs[buf][kk][tx * 8 + 4];
#pragma unroll
            for (int i = 0; i < 8; i++)
#pragma unroll
                for (int j = 0; j < 8; j++) acc[i][j] += a[i] * b[j];
        }

        const int nb = buf ^ 1;
        As[nb][lk+0][lm] = ra0.x; As[nb][lk+1][lm] = ra0.y; As[nb][lk+2][lm] = ra0.z; As[nb][lk+3][lm] = ra0.w;
        As[nb][lk+0][lm+64] = ra1.x; As[nb][lk+1][lm+64] = ra1.y; As[nb][lk+2][lm+64] = ra1.z; As[nb][lk+3][lm+64] = ra1.w;
        Bs[nb][lk+0][lm] = rb0.x; Bs[nb][lk+1][lm] = rb0.y; Bs[nb][lk+2][lm] = rb0.z; Bs[nb][lk+3][lm] = rb0.w;
        Bs[nb][lk+0][lm+64] = rb1.x; Bs[nb][lk+1][lm+64] = rb1.y; Bs[nb][lk+2][lm+64] = rb1.z; Bs[nb][lk+3][lm+64] = rb1.w;
        __syncthreads();
        buf = nb;
    }

#pragma unroll
    for (int kk = 0; kk < BK; kk++) {
        float a[8], b[8];
        *(float4*)(a)     = *(const float4*)&As[buf][kk][ty * 8];
        *(float4*)(a + 4) = *(const float4*)&As[buf][kk][ty * 8 + 4];
        *(float4*)(b)     = *(const float4*)&Bs[buf][kk][tx * 8];
        *(float4*)(b + 4) = *(const float4*)&Bs[buf][kk][tx * 8 + 4];
#pragma unroll
        for (int i = 0; i < 8; i++)
#pragma unroll
            for (int j = 0; j < 8; j++) acc[i][j] += a[i] * b[j];
    }

#pragma unroll
    for (int i = 0; i < 8; i++) {
        int m = bm + ty * 8 + i;
        int b = m >> 10, pos = m & 1023;
#pragma unroll
        for (int j = 0; j < 8; j++) {
            int n = bn + tx * 8 + j;
            int h = n >> 6, d = n & 63;
            if (which == 0) {
                g_q[((size_t)(b * HH + h) * NN + pos) * DH + d] = acc[i][j];
            } else if (which == 1) {
                g_k[((size_t)(b * HH + h) * JJ + NUM_MEM + pos) * DH + d] = acc[i][j];
            } else {
                g_v[((size_t)(b * HH + h) * JJ + NUM_MEM + pos) * DH + d] = acc[i][j];
            }
        }
    }
}

// ---------------- kernel 2b: output projection GEMM (A = g_ctx, C = out + bias) ----------
__global__ __launch_bounds__(256, 2)
void out_gemm(const float* __restrict__ Bw, const float* __restrict__ bias, float* __restrict__ C) {
    constexpr int K = 1024;
    constexpr int BK = 16;
    const float* Ap = (const float*)g_ctx;

    const int bm = blockIdx.y * 128;
    const int bn = blockIdx.x * 128;

    __shared__ __align__(16) float As[2][BK][LDS_PAD];
    __shared__ __align__(16) float Bs[2][BK][LDS_PAD];

    const int tid = threadIdx.x;
    const int tx = tid & 15, ty = tid >> 4;
    const int lm = tid >> 2;
    const int lk = (tid & 3) << 2;

    const float* Ald = Ap + (size_t)(bm + lm) * K + lk;
    const float* Bld = Bw + (size_t)(bn + lm) * K + lk;
    const size_t half = (size_t)64 * K;

    float4 ra0 = *(const float4*)(Ald);
    float4 ra1 = *(const float4*)(Ald + half);
    float4 rb0 = *(const float4*)(Bld);
    float4 rb1 = *(const float4*)(Bld + half);

    float acc[8][8];
#pragma unroll
    for (int i = 0; i < 8; i++)
#pragma unroll
        for (int j = 0; j < 8; j++) acc[i][j] = 0.f;

    As[0][lk+0][lm] = ra0.x; As[0][lk+1][lm] = ra0.y; As[0][lk+2][lm] = ra0.z; As[0][lk+3][lm] = ra0.w;
    As[0][lk+0][lm+64] = ra1.x; As[0][lk+1][lm+64] = ra1.y; As[0][lk+2][lm+64] = ra1.z; As[0][lk+3][lm+64] = ra1.w;
    Bs[0][lk+0][lm] = rb0.x; Bs[0][lk+1][lm] = rb0.y; Bs[0][lk+2][lm] = rb0.z; Bs[0][lk+3][lm] = rb0.w;
    Bs[0][lk+0][lm+64] = rb1.x; Bs[0][lk+1][lm+64] = rb1.y; Bs[0][lk+2][lm+64] = rb1.z; Bs[0][lk+3][lm+64] = rb1.w;
    __syncthreads();

    int buf = 0;
    for (int t = 1; t < K / BK; t++) {
        const float* A2 = Ald + t * BK;
        const float* B2 = Bld + t * BK;
        ra0 = *(const float4*)(A2);
        ra1 = *(const float4*)(A2 + half);
        rb0 = *(const float4*)(B2);
        rb1 = *(const float4*)(B2 + half);

#pragma unroll
        for (int kk = 0; kk < BK; kk++) {
            float a[8], b[8];
            *(float4*)(a)     = *(const float4*)&As[buf][kk][ty * 8];
            *(float4*)(a + 4) = *(const float4*)&As[buf][kk][ty * 8 + 4];
            *(float4*)(b)     = *(const float4*)&Bs[buf][kk][tx * 8];
            *(float4*)(b + 4) = *(const float4*)&Bs[buf][kk][tx * 8 + 4];
#pragma unroll
            for (int i = 0; i < 8; i++)
#pragma unroll
                for (int j = 0; j < 8; j++) acc[i][j] += a[i] * b[j];
        }

        const int nb = buf ^ 1;
        As[nb][lk+0][lm] = ra0.x; As[nb][lk+1][lm] = ra0.y; As[nb][lk+2][lm] = ra0.z; As[nb][lk+3][lm] = ra0.w;
        As[nb][lk+0][lm+64] = ra1.x; As[nb][lk+1][lm+64] = ra1.y; As[nb][lk+2][lm+64] = ra1.z; As[nb][lk+3][lm+64] = ra1.w;
        Bs[nb][lk+0][lm] = rb0.x; Bs[nb][lk+1][lm] = rb0.y; Bs[nb][lk+2][lm] = rb0.z; Bs[nb][lk+3][lm] = rb0.w;
        Bs[nb][lk+0][lm+64] = rb1.x; Bs[nb][lk+1][lm+64] = rb1.y; Bs[nb][lk+2][lm+64] = rb1.z; Bs[nb][lk+3][lm+64] = rb1.w;
        __syncthreads();
        buf = nb;
    }

#pragma unroll
    for (int kk = 0; kk < BK; kk++) {
        float a[8], b[8];
        *(float4*)(a)     = *(const float4*)&As[buf][kk][ty * 8];
        *(float4*)(a + 4) = *(const float4*)&As[buf][kk][ty * 8 + 4];
        *(float4*)(b)     = *(const float4*)&Bs[buf][kk][tx * 8];
        *(float4*)(b + 4) = *(const float4*)&Bs[buf][kk][tx * 8 + 4];
#pragma unroll
        for (int i = 0; i < 8; i++)
#pragma unroll
            for (int j = 0; j < 8; j++) acc[i][j] += a[i] * b[j];
    }

#pragma unroll
    for (int i = 0; i < 8; i++) {
        int m = bm + ty * 8 + i;
#pragma unroll
        for (int j = 0; j < 8; j++) {
            int n = bn + tx * 8 + j;
            C[(size_t)m * 1024 + n] = acc[i][j] + bias[n];
        }
    }
}

// ---------------- kernel 3: raw dots = SCALE * Q @ K^T, 128x64 tiles (8x4/thread) -------
// grid = (17 j-tiles, 8 i-tiles, 64 bh). Skip tile if j0 > i0 + 191.
// Tiles in DYNAMIC shared memory (50 KB > 48 KB static limit; attribute set on host).
#define DOTS_SMEM ((64 * 132 + 64 * 68) * 4)   // 51200 bytes
__global__ __launch_bounds__(256)
void dots_gemm() {
    extern __shared__ float dsm[];
    float (*Qs)[132] = (float(*)[132])dsm;            // [d][i], 128 rows
    float (*Ks)[68]  = (float(*)[68])(dsm + 64 * 132); // [d][j]

    const int bh = blockIdx.z;
    const int i0 = blockIdx.y * 128;
    const int j0 = blockIdx.x * 64;
    if (j0 > i0 + 191) return;

    const float* Qp = g_q + ((size_t)bh * NN + i0) * DH;
    const float* Kp = g_k + ((size_t)bh * JJ + j0) * DH;

    const int tid = threadIdx.x;
    for (int f = tid; f < 2048; f += 256) {
        int r = f >> 4, dq = (f & 15) << 2;
        float4 q4 = *(const float4*)(Qp + (size_t)r * DH + dq);
        Qs[dq + 0][r] = q4.x; Qs[dq + 1][r] = q4.y; Qs[dq + 2][r] = q4.z; Qs[dq + 3][r] = q4.w;
    }
    for (int f = tid; f < 1024; f += 256) {
        int r = f >> 4, dq = (f & 15) << 2;
        float4 k4 = *(const float4*)(Kp + (size_t)r * DH + dq);
        Ks[dq + 0][r] = k4.x; Ks[dq + 1][r] = k4.y; Ks[dq + 2][r] = k4.z; Ks[dq + 3][r] = k4.w;
    }
    __syncthreads();

    const int tx = tid & 15, ty = tid >> 4;
    float acc[8][4];
#pragma unroll
    for (int i = 0; i < 8; i++)
#pragma unroll
        for (int j = 0; j < 4; j++) acc[i][j] = 0.f;

#pragma unroll 8
    for (int d = 0; d < 64; d++) {
        float a[8], b[4];
#pragma unroll
        for (int i = 0; i < 8; i++) a[i] = Qs[d][ty * 8 + i];
#pragma unroll
        for (int j = 0; j < 4; j++) b[j] = Ks[d][tx * 4 + j];
#pragma unroll
        for (int i = 0; i < 8; i++)
#pragma unroll
            for (int j = 0; j < 4; j++) acc[i][j] += a[i] * b[j];
    }

    size_t ob = ((size_t)bh * NN + i0 + ty * 8) * JJ + j0 + tx * 4;
#pragma unroll
    for (int i = 0; i < 8; i++)
#pragma unroll
        for (int j = 0; j < 4; j++)
            g_raw[ob + (size_t)i * JJ + j] = acc[i][j] * SCALEF;
}

// ---------------- kernel 4: pre-softmax talking heads (valid j range only) ----------------
__global__ __launch_bounds__(256)
void premix_kernel(const float* __restrict__ pre_proj) {
    const int b = blockIdx.x >> 10;
    const int i = blockIdx.x & 1023;
    __shared__ float pp[256];
    if (threadIdx.x < 256) pp[threadIdx.x] = pre_proj[threadIdx.x];
    __syncthreads();

    const int jlen = i + NUM_MEM + 1;
    const size_t base = ((size_t)b * HH * NN + i) * JJ;
    const size_t hs = (size_t)NN * JJ;

    for (int j = threadIdx.x; j < jlen; j += 256) {
        float r[HH];
#pragma unroll
        for (int h = 0; h < HH; h++) r[h] = g_raw[base + (size_t)h * hs + j];
#pragma unroll
        for (int kk = 0; kk < HH; kk++) {
            float s = 0.f;
#pragma unroll
            for (int h = 0; h < HH; h++) s += r[h] * pp[h * HH + kk];
            g_mix[base + (size_t)kk * hs + j] = s;
        }
    }
}

// ---------------- kernel 5: exact top-k (radix select) + softmax + post-mix ----------------
__global__ __launch_bounds__(512, 2)
void topk_kernel(const float* __restrict__ post_proj) {
    extern __shared__ float sm[];
    float* rows = sm;                                  // 16 * JROW floats
    unsigned* hist = (unsigned*)(sm + HH * JROW);      // 16 * 256 uints
    __shared__ float s_post[256];

    const int b = blockIdx.x >> 10;
    const int i = blockIdx.x & 1023;
    const int tid = threadIdx.x;
    const int w = tid >> 5, lane = tid & 31;
    if (tid < 256) s_post[tid] = post_proj[tid];

    const int jlen = i + NUM_MEM + 1;
    float* srow = rows + w * JROW;
    unsigned* myh = hist + w * 256;
    const size_t base = ((size_t)(b * HH + w) * NN + i) * JJ;

    float m = NEGMAX;
    for (int j = lane; j < jlen; j += 32) {
        float v = g_mix[base + j];
        srow[j] = v;
        m = fmaxf(m, v);
    }
#pragma unroll
    for (int o = 16; o; o >>= 1) m = fmaxf(m, __shfl_xor_sync(0xffffffffu, m, o));

    unsigned prefix = 0;
    int r = TOPKK;
#pragma unroll
    for (int shift = 24; shift >= 0; shift -= 8) {
        for (int t = lane; t < 256; t += 32) myh[t] = 0;
        __syncwarp();
        unsigned pm = (shift == 24) ? 0u : (0xFFFFFFFFu << (shift + 8));
        for (int j = lane; j < jlen; j += 32) {
            unsigned kx = fkey(srow[j]);
            if ((kx & pm) == prefix) atomicAdd(&myh[(kx >> shift) & 255u], 1u);
        }
        __syncwarp();
        unsigned tot = 0;
#pragma unroll
        for (int t = 0; t < 8; t++) tot += myh[lane * 8 + t];
        unsigned s = tot;
#pragma unroll
        for (int o = 1; o < 32; o <<= 1) {
            unsigned tt = __shfl_down_sync(0xffffffffu, s, o);
            if (lane + o < 32) s += tt;
        }
        unsigned s_strict = s - tot;
        bool sel = ((unsigned)r > s_strict) && ((unsigned)r <= s);
        unsigned bal = __ballot_sync(0xffffffffu, sel);
        int sl = __ffs(bal) - 1;
        unsigned pick = 0; int newr = r;
        if (sel) {
            int rr = r - (int)s_strict;
#pragma unroll
            for (int t = 7; t >= 0; t--) {
                unsigned c = myh[lane * 8 + t];
                if (rr <= (int)c) { pick = (unsigned)(lane * 8 + t); newr = rr; break; }
                rr -= (int)c;
            }
        }
        pick = __shfl_sync(0xffffffffu, pick, sl);
        r    = __shfl_sync(0xffffffffu, newr, sl);
        prefix |= pick << shift;
    }

    float sum = 0.f;
    for (int j = lane; j < JJ; j += 32) {
        float e = 0.f;
        if (j < jlen) {
            float v = srow[j];
            if (fkey(v) >= prefix) e = expf(v - m);
        }
        srow[j] = e;
        sum += e;
    }
#pragma unroll
    for (int o = 16; o; o >>= 1) sum += __shfl_xor_sync(0xffffffffu, sum, o);
    float inv = 1.0f / sum;
    for (int j = lane; j < JJ; j += 32) srow[j] *= inv;

    __syncthreads();

    // Phase C: post-mix. av_gemm (128-row tiles) reads k < min(JJ, (i/128)*128 + 192),
    // so write exactly that range (zeros beyond jlen) — output bit-identical.
    const int wlim = min(JJ, (i & ~127) + 192);
    const size_t ob = ((size_t)(b * HH) * NN + i) * JJ;
    const size_t hs = (size_t)NN * JJ;
    for (int j = tid; j < wlim; j += 512) {
        float a[HH];
#pragma unroll
        for (int hh = 0; hh < HH; hh++) a[hh] = rows[hh * JROW + j];
#pragma unroll
        for (int kk = 0; kk < HH; kk++) {
            float sacc = 0.f;
#pragma unroll
            for (int hh = 0; hh < HH; hh++) sacc += a[hh] * s_post[hh * 16 + kk];
            g_raw[ob + (size_t)kk * hs + j] = sacc;
        }
    }
}

// ---------------- kernel 6: context = attn2 @ V, 128x64 tiles (8x4/thread), pipelined ----
// grid = (1, 8 i-tiles, 64 bh). kmax = min(JJ, i0 + 192) matches topk's wlim.
__global__ __launch_bounds__(256)
void av_gemm() {
    const int bh = blockIdx.z;
    const int b = bh >> 4, h = bh & 15;
    const int i0 = blockIdx.y * 128;

    const float* Ap = g_raw + ((size_t)bh * NN + i0) * JJ;
    const float* Vp = g_v + (size_t)bh * JJ * DH;
    const int kmax = min(JJ, i0 + 192);

    __shared__ float As[16][132];  // [k][i], 128 rows
    __shared__ float Bs[16][68];   // [k][d]

    const int tid = threadIdx.x;
    const int tx = tid & 15, ty = tid >> 4;
    const int ar = tid >> 1, ak8 = (tid & 1) << 3;     // A loader: row 0..127, k-octet
    const int br = tid >> 4, bdq = (tid & 15) << 2;    // B loader: k-row 0..15, d-quad

    float acc[8][4];
#pragma unroll
    for (int i = 0; i < 8; i++)
#pragma unroll
        for (int j = 0; j < 4; j++) acc[i][j] = 0.f;

    // prefetch first slice
    float4 a4a = *(const float4*)(Ap + (size_t)ar * JJ + ak8);
    float4 a4b = *(const float4*)(Ap + (size_t)ar * JJ + ak8 + 4);
    float4 b4  = *(const float4*)(Vp + (size_t)br * DH + bdq);

    for (int kt = 0; kt < kmax; kt += 16) {
        __syncthreads();
        As[ak8 + 0][ar] = a4a.x; As[ak8 + 1][ar] = a4a.y; As[ak8 + 2][ar] = a4a.z; As[ak8 + 3][ar] = a4a.w;
        As[ak8 + 4][ar] = a4b.x; As[ak8 + 5][ar] = a4b.y; As[ak8 + 6][ar] = a4b.z; As[ak8 + 7][ar] = a4b.w;
        *(float4*)&Bs[br][bdq] = b4;
        __syncthreads();

        if (kt + 16 < kmax) {
            a4a = *(const float4*)(Ap + (size_t)ar * JJ + kt + 16 + ak8);
            a4b = *(const float4*)(Ap + (size_t)ar * JJ + kt + 16 + ak8 + 4);
            b4  = *(const float4*)(Vp + (size_t)(kt + 16 + br) * DH + bdq);
        }

#pragma unroll
        for (int kk = 0; kk < 16; kk++) {
            float a[8], bb[4];
#pragma unroll
            for (int i = 0; i < 8; i++) a[i] = As[kk][ty * 8 + i];
#pragma unroll
            for (int j = 0; j < 4; j++) bb[j] = Bs[kk][tx * 4 + j];
#pragma unroll
            for (int i = 0; i < 8; i++)
#pragma unroll
                for (int j = 0; j < 4; j++) acc[i][j] += a[i] * bb[j];
        }
    }

    const int irow = i0 + ty * 8;
    const int d0 = h * DH + tx * 4;
#pragma unroll
    for (int i = 0; i < 8; i++)
#pragma unroll
        for (int j = 0; j < 4; j++)
            g_ctx[((size_t)b * NN + irow + i) * DIMM + d0 + j] = acc[i][j];
}

// ---------------- host launcher ----------------
extern "C" void kernel_launch(void* const* d_in, const int* in_sizes, int n_in,
                              void* d_out, int out_size) {
    const float* x        = (const float*)d_in[0];
    const float* Wq       = (const float*)d_in[1];
    const float* Wk       = (const float*)d_in[2];
    const float* Wv       = (const float*)d_in[3];
    const float* pre_proj = (const float*)d_in[4];
    const float* post_proj= (const float*)d_in[5];
    const float* mem_k    = (const float*)d_in[6];
    const float* mem_v    = (const float*)d_in[7];
    const float* Wout     = (const float*)d_in[8];
    const float* bout     = (const float*)d_in[9];
    float* out = (float*)d_out;
    (void)in_sizes; (void)n_in; (void)out_size;

    const int topk_smem = (HH * JROW + HH * 256) * 4;  // 86,080 bytes
    cudaFuncSetAttribute(topk_kernel, cudaFuncAttributeMaxDynamicSharedMemorySize, topk_smem);
    cudaFuncSetAttribute(dots_gemm, cudaFuncAttributeMaxDynamicSharedMemorySize, DOTS_SMEM);

    fill_mem_kernel<<<64, 1024>>>(mem_k, mem_v);

    qkv_gemm<<<dim3(24, 32), 256>>>(x, Wq, Wk, Wv);

    dots_gemm<<<dim3(17, 8, 64), 256, DOTS_SMEM>>>();

    premix_kernel<<<BB * NN, 256>>>(pre_proj);

    topk_kernel<<<BB * NN, 512, topk_smem>>>(post_proj);

    av_gemm<<<dim3(1, 8, 64), 256>>>();

    out_gemm<<<dim3(8, 32), 256>>>(Wout, bout, out);
}

// round 13
// speedup vs baseline: 1.2802x; 1.0233x over previous
#include <cuda_runtime.h>
#include <math.h>
#include <stdint.h>

// ---------------- problem constants ----------------
#define BB 4
#define NN 1024
#define DIMM 1024
#define HH 16
#define DH 64
#define NUM_MEM 64
#define JJ (NN + NUM_MEM)   // 1088
#define TOPKK 64
#define SCALEF 0.125f
#define NEGMAX (-3.402823466e38f)
#define JROW 1089           // padded row stride in shared

// ---------------- device scratch (allocation-free) ----------------
__device__ float g_q  [(size_t)BB*HH*NN*DH];
__device__ float g_k  [(size_t)BB*HH*JJ*DH];
__device__ float g_v  [(size_t)BB*HH*JJ*DH];
__device__ float g_raw[(size_t)BB*HH*NN*JJ];   // raw dots -> (reused) post-mixed attn
__device__ float g_mix[(size_t)BB*HH*NN*JJ];   // pre-mixed dots (only j < jlen valid)
__device__ float g_ctx[(size_t)BB*NN*DIMM];

// monotone fp32 -> uint32 key (order-preserving)
__device__ __forceinline__ unsigned fkey(float f) {
    unsigned u = __float_as_uint(f);
    return (u & 0x80000000u) ? ~u : (u | 0x80000000u);
}

// ---------------- kernel 1: broadcast memory K/V into the kv cache ----------------
__global__ void fill_mem_kernel(const float* __restrict__ mk, const float* __restrict__ mv) {
    int idx = blockIdx.x * blockDim.x + threadIdx.x;
    if (idx >= HH * NUM_MEM * DH) return;
    int h    = idx / (NUM_MEM * DH);
    int rest = idx % (NUM_MEM * DH);
    float kv = mk[idx], vv = mv[idx];
#pragma unroll
    for (int b = 0; b < BB; b++) {
        size_t o = ((size_t)(b * HH + h) * JJ) * DH + rest;
        g_k[o] = kv;
        g_v[o] = vv;
    }
}

#define LDS_PAD 132

// ---------------- kernel 2a: MERGED QKV projection GEMM ----------------
__global__ __launch_bounds__(256, 2)
void qkv_gemm(const float* __restrict__ x, const float* __restrict__ Wq,
              const float* __restrict__ Wk, const float* __restrict__ Wv) {
    constexpr int K = 1024;
    constexpr int BK = 16;

    const int bn3 = blockIdx.x * 128;          // 0..2944
    const int which = bn3 >> 10;               // 0=q, 1=k, 2=v
    const int bn = bn3 & 1023;                 // column within the selected matrix
    const float* Bw = (which == 0) ? Wq : (which == 1) ? Wk : Wv;
    const int bm = blockIdx.y * 128;

    __shared__ __align__(16) float As[2][BK][LDS_PAD];
    __shared__ __align__(16) float Bs[2][BK][LDS_PAD];

    const int tid = threadIdx.x;
    const int tx = tid & 15, ty = tid >> 4;
    const int lm = tid >> 2;
    const int lk = (tid & 3) << 2;

    const float* Ald = x + (size_t)(bm + lm) * K + lk;
    const float* Bld = Bw + (size_t)(bn + lm) * K + lk;
    const size_t half = (size_t)64 * K;

    float4 ra0 = *(const float4*)(Ald);
    float4 ra1 = *(const float4*)(Ald + half);
    float4 rb0 = *(const float4*)(Bld);
    float4 rb1 = *(const float4*)(Bld + half);

    float acc[8][8];
#pragma unroll
    for (int i = 0; i < 8; i++)
#pragma unroll
        for (int j = 0; j < 8; j++) acc[i][j] = 0.f;

    As[0][lk+0][lm] = ra0.x; As[0][lk+1][lm] = ra0.y; As[0][lk+2][lm] = ra0.z; As[0][lk+3][lm] = ra0.w;
    As[0][lk+0][lm+64] = ra1.x; As[0][lk+1][lm+64] = ra1.y; As[0][lk+2][lm+64] = ra1.z; As[0][lk+3][lm+64] = ra1.w;
    Bs[0][lk+0][lm] = rb0.x; Bs[0][lk+1][lm] = rb0.y; Bs[0][lk+2][lm] = rb0.z; Bs[0][lk+3][lm] = rb0.w;
    Bs[0][lk+0][lm+64] = rb1.x; Bs[0][lk+1][lm+64] = rb1.y; Bs[0][lk+2][lm+64] = rb1.z; Bs[0][lk+3][lm+64] = rb1.w;
    __syncthreads();

    int buf = 0;
    for (int t = 1; t < K / BK; t++) {
        const float* A2 = Ald + t * BK;
        const float* B2 = Bld + t * BK;
        ra0 = *(const float4*)(A2);
        ra1 = *(const float4*)(A2 + half);
        rb0 = *(const float4*)(B2);
        rb1 = *(const float4*)(B2 + half);

#pragma unroll
        for (int kk = 0; kk < BK; kk++) {
            float a[8], b[8];
            *(float4*)(a)     = *(const float4*)&As[buf][kk][ty * 8];
            *(float4*)(a + 4) = *(const float4*)&As[buf][kk][ty * 8 + 4];
            *(float4*)(b)     = *(const float4*)&Bs[buf][kk][tx * 8];
            *(float4*)(b + 4) = *(const float4*)&Bs[buf][kk][tx * 8 + 4];
#pragma unroll
            for (int i = 0; i < 8; i++)
#pragma unroll
                for (int j = 0; j < 8; j++) acc[i][j] += a[i] * b[j];
        }

        const int nb = buf ^ 1;
        As[nb][lk+0][lm] = ra0.x; As[nb][lk+1][lm] = ra0.y; As[nb][lk+2][lm] = ra0.z; As[nb][lk+3][lm] = ra0.w;
        As[nb][lk+0][lm+64] = ra1.x; As[nb][lk+1][lm+64] = ra1.y; As[nb][lk+2][lm+64] = ra1.z; As[nb][lk+3][lm+64] = ra1.w;
        Bs[nb][lk+0][lm] = rb0.x; Bs[nb][lk+1][lm] = rb0.y; Bs[nb][lk+2][lm] = rb0.z; Bs[nb][lk+3][lm] = rb0.w;
        Bs[nb][lk+0][lm+64] = rb1.x; Bs[nb][lk+1][lm+64] = rb1.y; Bs[nb][lk+2][lm+64] = rb1.z; Bs[nb][lk+3][lm+64] = rb1.w;
        __syncthreads();
        buf = nb;
    }

#pragma unroll
    for (int kk = 0; kk < BK; kk++) {
        float a[8], b[8];
        *(float4*)(a)     = *(const float4*)&As[buf][kk][ty * 8];
        *(float4*)(a + 4) = *(const float4*)&As[buf][kk][ty * 8 + 4];
        *(float4*)(b)     = *(const float4*)&Bs[buf][kk][tx * 8];
        *(float4*)(b + 4) = *(const float4*)&Bs[buf][kk][tx * 8 + 4];
#pragma unroll
        for (int i = 0; i < 8; i++)
#pragma unroll
            for (int j = 0; j < 8; j++) acc[i][j] += a[i] * b[j];
    }

#pragma unroll
    for (int i = 0; i < 8; i++) {
        int m = bm + ty * 8 + i;
        int b = m >> 10, pos = m & 1023;
#pragma unroll
        for (int j = 0; j < 8; j++) {
            int n = bn + tx * 8 + j;
            int h = n >> 6, d = n & 63;
            if (which == 0) {
                g_q[((size_t)(b * HH + h) * NN + pos) * DH + d] = acc[i][j];
            } else if (which == 1) {
                g_k[((size_t)(b * HH + h) * JJ + NUM_MEM + pos) * DH + d] = acc[i][j];
            } else {
                g_v[((size_t)(b * HH + h) * JJ + NUM_MEM + pos) * DH + d] = acc[i][j];
            }
        }
    }
}

// ---------------- kernel 2b: output projection GEMM (A = g_ctx, C = out + bias) ----------
__global__ __launch_bounds__(256, 2)
void out_gemm(const float* __restrict__ Bw, const float* __restrict__ bias, float* __restrict__ C) {
    constexpr int K = 1024;
    constexpr int BK = 16;
    const float* Ap = (const float*)g_ctx;

    const int bm = blockIdx.y * 128;
    const int bn = blockIdx.x * 128;

    __shared__ __align__(16) float As[2][BK][LDS_PAD];
    __shared__ __align__(16) float Bs[2][BK][LDS_PAD];

    const int tid = threadIdx.x;
    const int tx = tid & 15, ty = tid >> 4;
    const int lm = tid >> 2;
    const int lk = (tid & 3) << 2;

    const float* Ald = Ap + (size_t)(bm + lm) * K + lk;
    const float* Bld = Bw + (size_t)(bn + lm) * K + lk;
    const size_t half = (size_t)64 * K;

    float4 ra0 = *(const float4*)(Ald);
    float4 ra1 = *(const float4*)(Ald + half);
    float4 rb0 = *(const float4*)(Bld);
    float4 rb1 = *(const float4*)(Bld + half);

    float acc[8][8];
#pragma unroll
    for (int i = 0; i < 8; i++)
#pragma unroll
        for (int j = 0; j < 8; j++) acc[i][j] = 0.f;

    As[0][lk+0][lm] = ra0.x; As[0][lk+1][lm] = ra0.y; As[0][lk+2][lm] = ra0.z; As[0][lk+3][lm] = ra0.w;
    As[0][lk+0][lm+64] = ra1.x; As[0][lk+1][lm+64] = ra1.y; As[0][lk+2][lm+64] = ra1.z; As[0][lk+3][lm+64] = ra1.w;
    Bs[0][lk+0][lm] = rb0.x; Bs[0][lk+1][lm] = rb0.y; Bs[0][lk+2][lm] = rb0.z; Bs[0][lk+3][lm] = rb0.w;
    Bs[0][lk+0][lm+64] = rb1.x; Bs[0][lk+1][lm+64] = rb1.y; Bs[0][lk+2][lm+64] = rb1.z; Bs[0][lk+3][lm+64] = rb1.w;
    __syncthreads();

    int buf = 0;
    for (int t = 1; t < K / BK; t++) {
        const float* A2 = Ald + t * BK;
        const float* B2 = Bld + t * BK;
        ra0 = *(const float4*)(A2);
        ra1 = *(const float4*)(A2 + half);
        rb0 = *(const float4*)(B2);
        rb1 = *(const float4*)(B2 + half);

#pragma unroll
        for (int kk = 0; kk < BK; kk++) {
            float a[8], b[8];
            *(float4*)(a)     = *(const float4*)&As[buf][kk][ty * 8];
            *(float4*)(a + 4) = *(const float4*)&As[buf][kk][ty * 8 + 4];
            *(float4*)(b)     = *(const float4*)&Bs[buf][kk][tx * 8];
            *(float4*)(b + 4) = *(const float4*)&Bs[buf][kk][tx * 8 + 4];
#pragma unroll
            for (int i = 0; i < 8; i++)
#pragma unroll
                for (int j = 0; j < 8; j++) acc[i][j] += a[i] * b[j];
        }

        const int nb = buf ^ 1;
        As[nb][lk+0][lm] = ra0.x; As[nb][lk+1][lm] = ra0.y; As[nb][lk+2][lm] = ra0.z; As[nb][lk+3][lm] = ra0.w;
        As[nb][lk+0][lm+64] = ra1.x; As[nb][lk+1][lm+64] = ra1.y; As[nb][lk+2][lm+64] = ra1.z; As[nb][lk+3][lm+64] = ra1.w;
        Bs[nb][lk+0][lm] = rb0.x; Bs[nb][lk+1][lm] = rb0.y; Bs[nb][lk+2][lm] = rb0.z; Bs[nb][lk+3][lm] = rb0.w;
        Bs[nb][lk+0][lm+64] = rb1.x; Bs[nb][lk+1][lm+64] = rb1.y; Bs[nb][lk+2][lm+64] = rb1.z; Bs[nb][lk+3][lm+64] = rb1.w;
        __syncthreads();
        buf = nb;
    }

#pragma unroll
    for (int kk = 0; kk < BK; kk++) {
        float a[8], b[8];
        *(float4*)(a)     = *(const float4*)&As[buf][kk][ty * 8];
        *(float4*)(a + 4) = *(const float4*)&As[buf][kk][ty * 8 + 4];
        *(float4*)(b)     = *(const float4*)&Bs[buf][kk][tx * 8];
        *(float4*)(b + 4) = *(const float4*)&Bs[buf][kk][tx * 8 + 4];
#pragma unroll
        for (int i = 0; i < 8; i++)
#pragma unroll
            for (int j = 0; j < 8; j++) acc[i][j] += a[i] * b[j];
    }

#pragma unroll
    for (int i = 0; i < 8; i++) {
        int m = bm + ty * 8 + i;
#pragma unroll
        for (int j = 0; j < 8; j++) {
            int n = bn + tx * 8 + j;
            C[(size_t)m * 1024 + n] = acc[i][j] + bias[n];
        }
    }
}

// ---------------- kernel 3: raw dots = SCALE * Q @ K^T, 128x64 tiles (8x4/thread) -------
#define DOTS_SMEM ((64 * 132 + 64 * 68) * 4)   // 51200 bytes
__global__ __launch_bounds__(256)
void dots_gemm() {
    extern __shared__ float dsm[];
    float (*Qs)[132] = (float(*)[132])dsm;            // [d][i], 128 rows
    float (*Ks)[68]  = (float(*)[68])(dsm + 64 * 132); // [d][j]

    const int bh = blockIdx.z;
    const int i0 = blockIdx.y * 128;
    const int j0 = blockIdx.x * 64;
    if (j0 > i0 + 191) return;

    const float* Qp = g_q + ((size_t)bh * NN + i0) * DH;
    const float* Kp = g_k + ((size_t)bh * JJ + j0) * DH;

    const int tid = threadIdx.x;
    for (int f = tid; f < 2048; f += 256) {
        int r = f >> 4, dq = (f & 15) << 2;
        float4 q4 = *(const float4*)(Qp + (size_t)r * DH + dq);
        Qs[dq + 0][r] = q4.x; Qs[dq + 1][r] = q4.y; Qs[dq + 2][r] = q4.z; Qs[dq + 3][r] = q4.w;
    }
    for (int f = tid; f < 1024; f += 256) {
        int r = f >> 4, dq = (f & 15) << 2;
        float4 k4 = *(const float4*)(Kp + (size_t)r * DH + dq);
        Ks[dq + 0][r] = k4.x; Ks[dq + 1][r] = k4.y; Ks[dq + 2][r] = k4.z; Ks[dq + 3][r] = k4.w;
    }
    __syncthreads();

    const int tx = tid & 15, ty = tid >> 4;
    float acc[8][4];
#pragma unroll
    for (int i = 0; i < 8; i++)
#pragma unroll
        for (int j = 0; j < 4; j++) acc[i][j] = 0.f;

#pragma unroll 8
    for (int d = 0; d < 64; d++) {
        float a[8], b[4];
#pragma unroll
        for (int i = 0; i < 8; i++) a[i] = Qs[d][ty * 8 + i];
#pragma unroll
        for (int j = 0; j < 4; j++) b[j] = Ks[d][tx * 4 + j];
#pragma unroll
        for (int i = 0; i < 8; i++)
#pragma unroll
            for (int j = 0; j < 4; j++) acc[i][j] += a[i] * b[j];
    }

    size_t ob = ((size_t)bh * NN + i0 + ty * 8) * JJ + j0 + tx * 4;
#pragma unroll
    for (int i = 0; i < 8; i++)
#pragma unroll
        for (int j = 0; j < 4; j++)
            g_raw[ob + (size_t)i * JJ + j] = acc[i][j] * SCALEF;
}

// ---------------- kernel 4: pre-softmax talking heads, SMEM-STAGED ----------------
// R12 profile: regs=255 (16 in-flight LDGs live), occ 10.6%, DRAM 26%. Stage a
// 16-head x 256-j tile in shared via coalesced per-head row loads; compute from LDS.
// Per-output h-order sum unchanged -> bit-identical.
__global__ __launch_bounds__(256)
void premix_kernel(const float* __restrict__ pre_proj) {
    __shared__ float pp[256];
    __shared__ float tile[HH][256];

    const int b = blockIdx.x >> 10;
    const int i = blockIdx.x & 1023;
    const int tid = threadIdx.x;
    if (tid < 256) pp[tid] = pre_proj[tid];

    const int jlen = i + NUM_MEM + 1;
    const size_t base = ((size_t)b * HH * NN + i) * JJ;
    const size_t hs = (size_t)NN * JJ;

    for (int j0 = 0; j0 < jlen; j0 += 256) {
        const int n = min(256, jlen - j0);
        __syncthreads();
#pragma unroll
        for (int h = 0; h < HH; h++) {
            if (tid < n) tile[h][tid] = g_raw[base + (size_t)h * hs + j0 + tid];
        }
        __syncthreads();
        if (tid < n) {
            float r[HH];
#pragma unroll
            for (int h = 0; h < HH; h++) r[h] = tile[h][tid];
#pragma unroll
            for (int kk = 0; kk < HH; kk++) {
                float s = 0.f;
#pragma unroll
                for (int h = 0; h < HH; h++) s += r[h] * pp[h * HH + kk];
                g_mix[base + (size_t)kk * hs + j0 + tid] = s;
            }
        }
    }
}

// ---------------- kernel 5: exact top-k (radix select) + softmax + post-mix ----------------
__global__ __launch_bounds__(512, 2)
void topk_kernel(const float* __restrict__ post_proj) {
    extern __shared__ float sm[];
    float* rows = sm;                                  // 16 * JROW floats
    unsigned* hist = (unsigned*)(sm + HH * JROW);      // 16 * 256 uints
    __shared__ float s_post[256];

    const int b = blockIdx.x >> 10;
    const int i = blockIdx.x & 1023;
    const int tid = threadIdx.x;
    const int w = tid >> 5, lane = tid & 31;
    if (tid < 256) s_post[tid] = post_proj[tid];

    const int jlen = i + NUM_MEM + 1;
    float* srow = rows + w * JROW;
    unsigned* myh = hist + w * 256;
    const size_t base = ((size_t)(b * HH + w) * NN + i) * JJ;

    float m = NEGMAX;
    for (int j = lane; j < jlen; j += 32) {
        float v = g_mix[base + j];
        srow[j] = v;
        m = fmaxf(m, v);
    }
#pragma unroll
    for (int o = 16; o; o >>= 1) m = fmaxf(m, __shfl_xor_sync(0xffffffffu, m, o));

    unsigned prefix = 0;
    int r = TOPKK;
#pragma unroll
    for (int shift = 24; shift >= 0; shift -= 8) {
        for (int t = lane; t < 256; t += 32) myh[t] = 0;
        __syncwarp();
        unsigned pm = (shift == 24) ? 0u : (0xFFFFFFFFu << (shift + 8));
        for (int j = lane; j < jlen; j += 32) {
            unsigned kx = fkey(srow[j]);
            if ((kx & pm) == prefix) atomicAdd(&myh[(kx >> shift) & 255u], 1u);
        }
        __syncwarp();
        unsigned tot = 0;
#pragma unroll
        for (int t = 0; t < 8; t++) tot += myh[lane * 8 + t];
        unsigned s = tot;
#pragma unroll
        for (int o = 1; o < 32; o <<= 1) {
            unsigned tt = __shfl_down_sync(0xffffffffu, s, o);
            if (lane + o < 32) s += tt;
        }
        unsigned s_strict = s - tot;
        bool sel = ((unsigned)r > s_strict) && ((unsigned)r <= s);
        unsigned bal = __ballot_sync(0xffffffffu, sel);
        int sl = __ffs(bal) - 1;
        unsigned pick = 0; int newr = r;
        if (sel) {
            int rr = r - (int)s_strict;
#pragma unroll
            for (int t = 7; t >= 0; t--) {
                unsigned c = myh[lane * 8 + t];
                if (rr <= (int)c) { pick = (unsigned)(lane * 8 + t); newr = rr; break; }
                rr -= (int)c;
            }
        }
        pick = __shfl_sync(0xffffffffu, pick, sl);
        r    = __shfl_sync(0xffffffffu, newr, sl);
        prefix |= pick << shift;
    }

    float sum = 0.f;
    for (int j = lane; j < JJ; j += 32) {
        float e = 0.f;
        if (j < jlen) {
            float v = srow[j];
            if (fkey(v) >= prefix) e = expf(v - m);
        }
        srow[j] = e;
        sum += e;
    }
#pragma unroll
    for (int o = 16; o; o >>= 1) sum += __shfl_xor_sync(0xffffffffu, sum, o);
    float inv = 1.0f / sum;
    for (int j = lane; j < JJ; j += 32) srow[j] *= inv;

    __syncthreads();

    // Phase C: post-mix. av_gemm (128-row tiles) reads k < min(JJ, (i/128)*128 + 192).
    const int wlim = min(JJ, (i & ~127) + 192);
    const size_t ob = ((size_t)(b * HH) * NN + i) * JJ;
    const size_t hs = (size_t)NN * JJ;
    for (int j = tid; j < wlim; j += 512) {
        float a[HH];
#pragma unroll
        for (int hh = 0; hh < HH; hh++) a[hh] = rows[hh * JROW + j];
#pragma unroll
        for (int kk = 0; kk < HH; kk++) {
            float sacc = 0.f;
#pragma unroll
            for (int hh = 0; hh < HH; hh++) sacc += a[hh] * s_post[hh * 16 + kk];
            g_raw[ob + (size_t)kk * hs + j] = sacc;
        }
    }
}

// ---------------- kernel 6: context = attn2 @ V, 128x64 tiles (8x4/thread), pipelined ----
__global__ __launch_bounds__(256)
void av_gemm() {
    const int bh = blockIdx.z;
    const int b = bh >> 4, h = bh & 15;
    const int i0 = blockIdx.y * 128;

    const float* Ap = g_raw + ((size_t)bh * NN + i0) * JJ;
    const float* Vp = g_v + (size_t)bh * JJ * DH;
    const int kmax = min(JJ, i0 + 192);

    __shared__ float As[16][132];  // [k][i], 128 rows
    __shared__ float Bs[16][68];   // [k][d]

    const int tid = threadIdx.x;
    const int tx = tid & 15, ty = tid >> 4;
    const int ar = tid >> 1, ak8 = (tid & 1) << 3;
    const int br = tid >> 4, bdq = (tid & 15) << 2;

    float acc[8][4];
#pragma unroll
    for (int i = 0; i < 8; i++)
#pragma unroll
        for (int j = 0; j < 4; j++) acc[i][j] = 0.f;

    float4 a4a = *(const float4*)(Ap + (size_t)ar * JJ + ak8);
    float4 a4b = *(const float4*)(Ap + (size_t)ar * JJ + ak8 + 4);
    float4 b4  = *(const float4*)(Vp + (size_t)br * DH + bdq);

    for (int kt = 0; kt < kmax; kt += 16) {
        __syncthreads();
        As[ak8 + 0][ar] = a4a.x; As[ak8 + 1][ar] = a4a.y; As[ak8 + 2][ar] = a4a.z; As[ak8 + 3][ar] = a4a.w;
        As[ak8 + 4][ar] = a4b.x; As[ak8 + 5][ar] = a4b.y; As[ak8 + 6][ar] = a4b.z; As[ak8 + 7][ar] = a4b.w;
        *(float4*)&Bs[br][bdq] = b4;
        __syncthreads();

        if (kt + 16 < kmax) {
            a4a = *(const float4*)(Ap + (size_t)ar * JJ + kt + 16 + ak8);
            a4b = *(const float4*)(Ap + (size_t)ar * JJ + kt + 16 + ak8 + 4);
            b4  = *(const float4*)(Vp + (size_t)(kt + 16 + br) * DH + bdq);
        }

#pragma unroll
        for (int kk = 0; kk < 16; kk++) {
            float a[8], bb[4];
#pragma unroll
            for (int i = 0; i < 8; i++) a[i] = As[kk][ty * 8 + i];
#pragma unroll
            for (int j = 0; j < 4; j++) bb[j] = Bs[kk][tx * 4 + j];
#pragma unroll
            for (int i = 0; i < 8; i++)
#pragma unroll
                for (int j = 0; j < 4; j++) acc[i][j] += a[i] * bb[j];
        }
    }

    const int irow = i0 + ty * 8;
    const int d0 = h * DH + tx * 4;
#pragma unroll
    for (int i = 0; i < 8; i++)
#pragma unroll
        for (int j = 0; j < 4; j++)
            g_ctx[((size_t)b * NN + irow + i) * DIMM + d0 + j] = acc[i][j];
}

// ---------------- host launcher ----------------
extern "C" void kernel_launch(void* const* d_in, const int* in_sizes, int n_in,
                              void* d_out, int out_size) {
    const float* x        = (const float*)d_in[0];
    const float* Wq       = (const float*)d_in[1];
    const float* Wk       = (const float*)d_in[2];
    const float* Wv       = (const float*)d_in[3];
    const float* pre_proj = (const float*)d_in[4];
    const float* post_proj= (const float*)d_in[5];
    const float* mem_k    = (const float*)d_in[6];
    const float* mem_v    = (const float*)d_in[7];
    const float* Wout     = (const float*)d_in[8];
    const float* bout     = (const float*)d_in[9];
    float* out = (float*)d_out;
    (void)in_sizes; (void)n_in; (void)out_size;

    const int topk_smem = (HH * JROW + HH * 256) * 4;  // 86,080 bytes
    cudaFuncSetAttribute(topk_kernel, cudaFuncAttributeMaxDynamicSharedMemorySize, topk_smem);
    cudaFuncSetAttribute(dots_gemm, cudaFuncAttributeMaxDynamicSharedMemorySize, DOTS_SMEM);

    fill_mem_kernel<<<64, 1024>>>(mem_k, mem_v);

    qkv_gemm<<<dim3(24, 32), 256>>>(x, Wq, Wk, Wv);

    dots_gemm<<<dim3(17, 8, 64), 256, DOTS_SMEM>>>();

    premix_kernel<<<BB * NN, 256>>>(pre_proj);

    topk_kernel<<<BB * NN, 512, topk_smem>>>(post_proj);

    av_gemm<<<dim3(1, 8, 64), 256>>>();

    out_gemm<<<dim3(8, 32), 256>>>(Wout, bout, out);
}

// round 14
// speedup vs baseline: 1.2835x; 1.0026x over previous
#include <cuda_runtime.h>
#include <math.h>
#include <stdint.h>

// ---------------- problem constants ----------------
#define BB 4
#define NN 1024
#define DIMM 1024
#define HH 16
#define DH 64
#define NUM_MEM 64
#define JJ (NN + NUM_MEM)   // 1088
#define TOPKK 64
#define SCALEF 0.125f
#define NEGMAX (-3.402823466e38f)
#define JROW 1089           // padded row stride in shared

// ---------------- device scratch (allocation-free) ----------------
__device__ float g_q  [(size_t)BB*HH*NN*DH];
__device__ float g_k  [(size_t)BB*HH*JJ*DH];
__device__ float g_v  [(size_t)BB*HH*JJ*DH];
__device__ float g_raw[(size_t)BB*HH*NN*JJ];   // raw dots -> (reused) post-mixed attn
__device__ float g_ctx[(size_t)BB*NN*DIMM];

// monotone fp32 -> uint32 key (order-preserving)
__device__ __forceinline__ unsigned fkey(float f) {
    unsigned u = __float_as_uint(f);
    return (u & 0x80000000u) ? ~u : (u | 0x80000000u);
}

// ---------------- kernel 1: broadcast memory K/V into the kv cache ----------------
__global__ void fill_mem_kernel(const float* __restrict__ mk, const float* __restrict__ mv) {
    int idx = blockIdx.x * blockDim.x + threadIdx.x;
    if (idx >= HH * NUM_MEM * DH) return;
    int h    = idx / (NUM_MEM * DH);
    int rest = idx % (NUM_MEM * DH);
    float kv = mk[idx], vv = mv[idx];
#pragma unroll
    for (int b = 0; b < BB; b++) {
        size_t o = ((size_t)(b * HH + h) * JJ) * DH + rest;
        g_k[o] = kv;
        g_v[o] = vv;
    }
}

#define LDS_PAD 132

// ---------------- kernel 2a: MERGED QKV projection GEMM ----------------
__global__ __launch_bounds__(256, 2)
void qkv_gemm(const float* __restrict__ x, const float* __restrict__ Wq,
              const float* __restrict__ Wk, const float* __restrict__ Wv) {
    constexpr int K = 1024;
    constexpr int BK = 16;

    const int bn3 = blockIdx.x * 128;          // 0..2944
    const int which = bn3 >> 10;               // 0=q, 1=k, 2=v
    const int bn = bn3 & 1023;                 // column within the selected matrix
    const float* Bw = (which == 0) ? Wq : (which == 1) ? Wk : Wv;
    const int bm = blockIdx.y * 128;

    __shared__ __align__(16) float As[2][BK][LDS_PAD];
    __shared__ __align__(16) float Bs[2][BK][LDS_PAD];

    const int tid = threadIdx.x;
    const int tx = tid & 15, ty = tid >> 4;
    const int lm = tid >> 2;
    const int lk = (tid & 3) << 2;

    const float* Ald = x + (size_t)(bm + lm) * K + lk;
    const float* Bld = Bw + (size_t)(bn + lm) * K + lk;
    const size_t half = (size_t)64 * K;

    float4 ra0 = *(const float4*)(Ald);
    float4 ra1 = *(const float4*)(Ald + half);
    float4 rb0 = *(const float4*)(Bld);
    float4 rb1 = *(const float4*)(Bld + half);

    float acc[8][8];
#pragma unroll
    for (int i = 0; i < 8; i++)
#pragma unroll
        for (int j = 0; j < 8; j++) acc[i][j] = 0.f;

    As[0][lk+0][lm] = ra0.x; As[0][lk+1][lm] = ra0.y; As[0][lk+2][lm] = ra0.z; As[0][lk+3][lm] = ra0.w;
    As[0][lk+0][lm+64] = ra1.x; As[0][lk+1][lm+64] = ra1.y; As[0][lk+2][lm+64] = ra1.z; As[0][lk+3][lm+64] = ra1.w;
    Bs[0][lk+0][lm] = rb0.x; Bs[0][lk+1][lm] = rb0.y; Bs[0][lk+2][lm] = rb0.z; Bs[0][lk+3][lm] = rb0.w;
    Bs[0][lk+0][lm+64] = rb1.x; Bs[0][lk+1][lm+64] = rb1.y; Bs[0][lk+2][lm+64] = rb1.z; Bs[0][lk+3][lm+64] = rb1.w;
    __syncthreads();

    int buf = 0;
    for (int t = 1; t < K / BK; t++) {
        const float* A2 = Ald + t * BK;
        const float* B2 = Bld + t * BK;
        ra0 = *(const float4*)(A2);
        ra1 = *(const float4*)(A2 + half);
        rb0 = *(const float4*)(B2);
        rb1 = *(const float4*)(B2 + half);

#pragma unroll
        for (int kk = 0; kk < BK; kk++) {
            float a[8], b[8];
            *(float4*)(a)     = *(const float4*)&As[buf][kk][ty * 8];
            *(float4*)(a + 4) = *(const float4*)&As[buf][kk][ty * 8 + 4];
            *(float4*)(b)     = *(const float4*)&Bs[buf][kk][tx * 8];
            *(float4*)(b + 4) = *(const float4*)&Bs[buf][kk][tx * 8 + 4];
#pragma unroll
            for (int i = 0; i < 8; i++)
#pragma unroll
                for (int j = 0; j < 8; j++) acc[i][j] += a[i] * b[j];
        }

        const int nb = buf ^ 1;
        As[nb][lk+0][lm] = ra0.x; As[nb][lk+1][lm] = ra0.y; As[nb][lk+2][lm] = ra0.z; As[nb][lk+3][lm] = ra0.w;
        As[nb][lk+0][lm+64] = ra1.x; As[nb][lk+1][lm+64] = ra1.y; As[nb][lk+2][lm+64] = ra1.z; As[nb][lk+3][lm+64] = ra1.w;
        Bs[nb][lk+0][lm] = rb0.x; Bs[nb][lk+1][lm] = rb0.y; Bs[nb][lk+2][lm] = rb0.z; Bs[nb][lk+3][lm] = rb0.w;
        Bs[nb][lk+0][lm+64] = rb1.x; Bs[nb][lk+1][lm+64] = rb1.y; Bs[nb][lk+2][lm+64] = rb1.z; Bs[nb][lk+3][lm+64] = rb1.w;
        __syncthreads();
        buf = nb;
    }

#pragma unroll
    for (int kk = 0; kk < BK; kk++) {
        float a[8], b[8];
        *(float4*)(a)     = *(const float4*)&As[buf][kk][ty * 8];
        *(float4*)(a + 4) = *(const float4*)&As[buf][kk][ty * 8 + 4];
        *(float4*)(b)     = *(const float4*)&Bs[buf][kk][tx * 8];
        *(float4*)(b + 4) = *(const float4*)&Bs[buf][kk][tx * 8 + 4];
#pragma unroll
        for (int i = 0; i < 8; i++)
#pragma unroll
            for (int j = 0; j < 8; j++) acc[i][j] += a[i] * b[j];
    }

#pragma unroll
    for (int i = 0; i < 8; i++) {
        int m = bm + ty * 8 + i;
        int b = m >> 10, pos = m & 1023;
#pragma unroll
        for (int j = 0; j < 8; j++) {
            int n = bn + tx * 8 + j;
            int h = n >> 6, d = n & 63;
            if (which == 0) {
                g_q[((size_t)(b * HH + h) * NN + pos) * DH + d] = acc[i][j];
            } else if (which == 1) {
                g_k[((size_t)(b * HH + h) * JJ + NUM_MEM + pos) * DH + d] = acc[i][j];
            } else {
                g_v[((size_t)(b * HH + h) * JJ + NUM_MEM + pos) * DH + d] = acc[i][j];
            }
        }
    }
}

// ---------------- kernel 2b: output projection GEMM (A = g_ctx, C = out + bias) ----------
__global__ __launch_bounds__(256, 2)
void out_gemm(const float* __restrict__ Bw, const float* __restrict__ bias, float* __restrict__ C) {
    constexpr int K = 1024;
    constexpr int BK = 16;
    const float* Ap = (const float*)g_ctx;

    const int bm = blockIdx.y * 128;
    const int bn = blockIdx.x * 128;

    __shared__ __align__(16) float As[2][BK][LDS_PAD];
    __shared__ __align__(16) float Bs[2][BK][LDS_PAD];

    const int tid = threadIdx.x;
    const int tx = tid & 15, ty = tid >> 4;
    const int lm = tid >> 2;
    const int lk = (tid & 3) << 2;

    const float* Ald = Ap + (size_t)(bm + lm) * K + lk;
    const float* Bld = Bw + (size_t)(bn + lm) * K + lk;
    const size_t half = (size_t)64 * K;

    float4 ra0 = *(const float4*)(Ald);
    float4 ra1 = *(const float4*)(Ald + half);
    float4 rb0 = *(const float4*)(Bld);
    float4 rb1 = *(const float4*)(Bld + half);

    float acc[8][8];
#pragma unroll
    for (int i = 0; i < 8; i++)
#pragma unroll
        for (int j = 0; j < 8; j++) acc[i][j] = 0.f;

    As[0][lk+0][lm] = ra0.x; As[0][lk+1][lm] = ra0.y; As[0][lk+2][lm] = ra0.z; As[0][lk+3][lm] = ra0.w;
    As[0][lk+0][lm+64] = ra1.x; As[0][lk+1][lm+64] = ra1.y; As[0][lk+2][lm+64] = ra1.z; As[0][lk+3][lm+64] = ra1.w;
    Bs[0][lk+0][lm] = rb0.x; Bs[0][lk+1][lm] = rb0.y; Bs[0][lk+2][lm] = rb0.z; Bs[0][lk+3][lm] = rb0.w;
    Bs[0][lk+0][lm+64] = rb1.x; Bs[0][lk+1][lm+64] = rb1.y; Bs[0][lk+2][lm+64] = rb1.z; Bs[0][lk+3][lm+64] = rb1.w;
    __syncthreads();

    int buf = 0;
    for (int t = 1; t < K / BK; t++) {
        const float* A2 = Ald + t * BK;
        const float* B2 = Bld + t * BK;
        ra0 = *(const float4*)(A2);
        ra1 = *(const float4*)(A2 + half);
        rb0 = *(const float4*)(B2);
        rb1 = *(const float4*)(B2 + half);

#pragma unroll
        for (int kk = 0; kk < BK; kk++) {
            float a[8], b[8];
            *(float4*)(a)     = *(const float4*)&As[buf][kk][ty * 8];
            *(float4*)(a + 4) = *(const float4*)&As[buf][kk][ty * 8 + 4];
            *(float4*)(b)     = *(const float4*)&Bs[buf][kk][tx * 8];
            *(float4*)(b + 4) = *(const float4*)&Bs[buf][kk][tx * 8 + 4];
#pragma unroll
            for (int i = 0; i < 8; i++)
#pragma unroll
                for (int j = 0; j < 8; j++) acc[i][j] += a[i] * b[j];
        }

        const int nb = buf ^ 1;
        As[nb][lk+0][lm] = ra0.x; As[nb][lk+1][lm] = ra0.y; As[nb][lk+2][lm] = ra0.z; As[nb][lk+3][lm] = ra0.w;
        As[nb][lk+0][lm+64] = ra1.x; As[nb][lk+1][lm+64] = ra1.y; As[nb][lk+2][lm+64] = ra1.z; As[nb][lk+3][lm+64] = ra1.w;
        Bs[nb][lk+0][lm] = rb0.x; Bs[nb][lk+1][lm] = rb0.y; Bs[nb][lk+2][lm] = rb0.z; Bs[nb][lk+3][lm] = rb0.w;
        Bs[nb][lk+0][lm+64] = rb1.x; Bs[nb][lk+1][lm+64] = rb1.y; Bs[nb][lk+2][lm+64] = rb1.z; Bs[nb][lk+3][lm+64] = rb1.w;
        __syncthreads();
        buf = nb;
    }

#pragma unroll
    for (int kk = 0; kk < BK; kk++) {
        float a[8], b[8];
        *(float4*)(a)     = *(const float4*)&As[buf][kk][ty * 8];
        *(float4*)(a + 4) = *(const float4*)&As[buf][kk][ty * 8 + 4];
        *(float4*)(b)     = *(const float4*)&Bs[buf][kk][tx * 8];
        *(float4*)(b + 4) = *(const float4*)&Bs[buf][kk][tx * 8 + 4];
#pragma unroll
        for (int i = 0; i < 8; i++)
#pragma unroll
            for (int j = 0; j < 8; j++) acc[i][j] += a[i] * b[j];
    }

#pragma unroll
    for (int i = 0; i < 8; i++) {
        int m = bm + ty * 8 + i;
#pragma unroll
        for (int j = 0; j < 8; j++) {
            int n = bn + tx * 8 + j;
            C[(size_t)m * 1024 + n] = acc[i][j] + bias[n];
        }
    }
}

// ---------------- kernel 3: raw dots = SCALE * Q @ K^T, 128x64 tiles (8x4/thread) -------
#define DOTS_SMEM ((64 * 132 + 64 * 68) * 4)   // 51200 bytes
__global__ __launch_bounds__(256)
void dots_gemm() {
    extern __shared__ float dsm[];
    float (*Qs)[132] = (float(*)[132])dsm;            // [d][i], 128 rows
    float (*Ks)[68]  = (float(*)[68])(dsm + 64 * 132); // [d][j]

    const int bh = blockIdx.z;
    const int i0 = blockIdx.y * 128;
    const int j0 = blockIdx.x * 64;
    if (j0 > i0 + 191) return;

    const float* Qp = g_q + ((size_t)bh * NN + i0) * DH;
    const float* Kp = g_k + ((size_t)bh * JJ + j0) * DH;

    const int tid = threadIdx.x;
    for (int f = tid; f < 2048; f += 256) {
        int r = f >> 4, dq = (f & 15) << 2;
        float4 q4 = *(const float4*)(Qp + (size_t)r * DH + dq);
        Qs[dq + 0][r] = q4.x; Qs[dq + 1][r] = q4.y; Qs[dq + 2][r] = q4.z; Qs[dq + 3][r] = q4.w;
    }
    for (int f = tid; f < 1024; f += 256) {
        int r = f >> 4, dq = (f & 15) << 2;
        float4 k4 = *(const float4*)(Kp + (size_t)r * DH + dq);
        Ks[dq + 0][r] = k4.x; Ks[dq + 1][r] = k4.y; Ks[dq + 2][r] = k4.z; Ks[dq + 3][r] = k4.w;
    }
    __syncthreads();

    const int tx = tid & 15, ty = tid >> 4;
    float acc[8][4];
#pragma unroll
    for (int i = 0; i < 8; i++)
#pragma unroll
        for (int j = 0; j < 4; j++) acc[i][j] = 0.f;

#pragma unroll 8
    for (int d = 0; d < 64; d++) {
        float a[8], b[4];
#pragma unroll
        for (int i = 0; i < 8; i++) a[i] = Qs[d][ty * 8 + i];
#pragma unroll
        for (int j = 0; j < 4; j++) b[j] = Ks[d][tx * 4 + j];
#pragma unroll
        for (int i = 0; i < 8; i++)
#pragma unroll
            for (int j = 0; j < 4; j++) acc[i][j] += a[i] * b[j];
    }

    size_t ob = ((size_t)bh * NN + i0 + ty * 8) * JJ + j0 + tx * 4;
#pragma unroll
    for (int i = 0; i < 8; i++)
#pragma unroll
        for (int j = 0; j < 4; j++)
            g_raw[ob + (size_t)i * JJ + j] = acc[i][j] * SCALEF;
}

// ---------------- kernel 5: FUSED pre-mix + top-k + softmax + post-mix ----------------
// Phase A stages 16x256 tiles of g_raw in the HIST region (dead during Phase A,
// identical 16 KB footprint; each radix pass re-zeroes it), mixes via s_pre, and
// writes mixed rows directly to shared — g_mix eliminated entirely.
__global__ __launch_bounds__(512, 2)
void topk_kernel(const float* __restrict__ pre_proj, const float* __restrict__ post_proj) {
    extern __shared__ float sm[];
    float* rows = sm;                                  // 16 * JROW floats
    unsigned* hist = (unsigned*)(sm + HH * JROW);      // 16 * 256 uints
    float* tile = (float*)hist;                        // Phase A staging (borrowed)
    __shared__ float s_pre[256];
    __shared__ float s_post[256];

    const int b = blockIdx.x >> 10;
    const int i = blockIdx.x & 1023;
    const int tid = threadIdx.x;
    const int w = tid >> 5, lane = tid & 31;
    if (tid < 256) { s_pre[tid] = pre_proj[tid]; s_post[tid] = post_proj[tid]; }
    __syncthreads();

    const int jlen = i + NUM_MEM + 1;
    const size_t rawbase = ((size_t)b * HH * NN + i) * JJ;
    const size_t hs = (size_t)NN * JJ;

    // ---- Phase A: smem-staged pre-mix, global g_raw -> shared rows ----
    for (int j0 = 0; j0 < jlen; j0 += 256) {
        const int n = min(256, jlen - j0);
        __syncthreads();
        for (int f = tid; f < HH * 256; f += 512) {
            int h = f >> 8, t = f & 255;
            if (t < n) tile[h * 256 + t] = g_raw[rawbase + (size_t)h * hs + j0 + t];
        }
        __syncthreads();
        if (tid < n) {
            float r[HH];
#pragma unroll
            for (int h = 0; h < HH; h++) r[h] = tile[h * 256 + tid];
#pragma unroll
            for (int kk = 0; kk < HH; kk++) {
                float s = 0.f;
#pragma unroll
                for (int h = 0; h < HH; h++) s += r[h] * s_pre[h * HH + kk];
                rows[kk * JROW + j0 + tid] = s;
            }
        }
    }
    __syncthreads();

    // ---- Phase B: warp w owns mixed head w ----
    float* srow = rows + w * JROW;
    unsigned* myh = hist + w * 256;

    float m = NEGMAX;
    for (int j = lane; j < jlen; j += 32) m = fmaxf(m, srow[j]);
#pragma unroll
    for (int o = 16; o; o >>= 1) m = fmaxf(m, __shfl_xor_sync(0xffffffffu, m, o));

    unsigned prefix = 0;
    int r = TOPKK;
#pragma unroll
    for (int shift = 24; shift >= 0; shift -= 8) {
        for (int t = lane; t < 256; t += 32) myh[t] = 0;
        __syncwarp();
        unsigned pm = (shift == 24) ? 0u : (0xFFFFFFFFu << (shift + 8));
        for (int j = lane; j < jlen; j += 32) {
            unsigned kx = fkey(srow[j]);
            if ((kx & pm) == prefix) atomicAdd(&myh[(kx >> shift) & 255u], 1u);
        }
        __syncwarp();
        unsigned tot = 0;
#pragma unroll
        for (int t = 0; t < 8; t++) tot += myh[lane * 8 + t];
        unsigned s = tot;
#pragma unroll
        for (int o = 1; o < 32; o <<= 1) {
            unsigned tt = __shfl_down_sync(0xffffffffu, s, o);
            if (lane + o < 32) s += tt;
        }
        unsigned s_strict = s - tot;
        bool sel = ((unsigned)r > s_strict) && ((unsigned)r <= s);
        unsigned bal = __ballot_sync(0xffffffffu, sel);
        int sl = __ffs(bal) - 1;
        unsigned pick = 0; int newr = r;
        if (sel) {
            int rr = r - (int)s_strict;
#pragma unroll
            for (int t = 7; t >= 0; t--) {
                unsigned c = myh[lane * 8 + t];
                if (rr <= (int)c) { pick = (unsigned)(lane * 8 + t); newr = rr; break; }
                rr -= (int)c;
            }
        }
        pick = __shfl_sync(0xffffffffu, pick, sl);
        r    = __shfl_sync(0xffffffffu, newr, sl);
        prefix |= pick << shift;
    }

    float sum = 0.f;
    for (int j = lane; j < JJ; j += 32) {
        float e = 0.f;
        if (j < jlen) {
            float v = srow[j];
            if (fkey(v) >= prefix) e = expf(v - m);
        }
        srow[j] = e;
        sum += e;
    }
#pragma unroll
    for (int o = 16; o; o >>= 1) sum += __shfl_xor_sync(0xffffffffu, sum, o);
    float inv = 1.0f / sum;
    for (int j = lane; j < JJ; j += 32) srow[j] *= inv;

    __syncthreads();

    // ---- Phase C: post-mix. av_gemm (128-row tiles) reads k < min(JJ, (i/128)*128+192) ----
    const int wlim = min(JJ, (i & ~127) + 192);
    const size_t ob = ((size_t)(b * HH) * NN + i) * JJ;
    for (int j = tid; j < wlim; j += 512) {
        float a[HH];
#pragma unroll
        for (int hh = 0; hh < HH; hh++) a[hh] = rows[hh * JROW + j];
#pragma unroll
        for (int kk = 0; kk < HH; kk++) {
            float sacc = 0.f;
#pragma unroll
            for (int hh = 0; hh < HH; hh++) sacc += a[hh] * s_post[hh * 16 + kk];
            g_raw[ob + (size_t)kk * hs + j] = sacc;
        }
    }
}

// ---------------- kernel 6: context = attn2 @ V, 128x64 tiles (8x4/thread), pipelined ----
__global__ __launch_bounds__(256)
void av_gemm() {
    const int bh = blockIdx.z;
    const int b = bh >> 4, h = bh & 15;
    const int i0 = blockIdx.y * 128;

    const float* Ap = g_raw + ((size_t)bh * NN + i0) * JJ;
    const float* Vp = g_v + (size_t)bh * JJ * DH;
    const int kmax = min(JJ, i0 + 192);

    __shared__ float As[16][132];  // [k][i], 128 rows
    __shared__ float Bs[16][68];   // [k][d]

    const int tid = threadIdx.x;
    const int tx = tid & 15, ty = tid >> 4;
    const int ar = tid >> 1, ak8 = (tid & 1) << 3;
    const int br = tid >> 4, bdq = (tid & 15) << 2;

    float acc[8][4];
#pragma unroll
    for (int i = 0; i < 8; i++)
#pragma unroll
        for (int j = 0; j < 4; j++) acc[i][j] = 0.f;

    float4 a4a = *(const float4*)(Ap + (size_t)ar * JJ + ak8);
    float4 a4b = *(const float4*)(Ap + (size_t)ar * JJ + ak8 + 4);
    float4 b4  = *(const float4*)(Vp + (size_t)br * DH + bdq);

    for (int kt = 0; kt < kmax; kt += 16) {
        __syncthreads();
        As[ak8 + 0][ar] = a4a.x; As[ak8 + 1][ar] = a4a.y; As[ak8 + 2][ar] = a4a.z; As[ak8 + 3][ar] = a4a.w;
        As[ak8 + 4][ar] = a4b.x; As[ak8 + 5][ar] = a4b.y; As[ak8 + 6][ar] = a4b.z; As[ak8 + 7][ar] = a4b.w;
        *(float4*)&Bs[br][bdq] = b4;
        __syncthreads();

        if (kt + 16 < kmax) {
            a4a = *(const float4*)(Ap + (size_t)ar * JJ + kt + 16 + ak8);
            a4b = *(const float4*)(Ap + (size_t)ar * JJ + kt + 16 + ak8 + 4);
            b4  = *(const float4*)(Vp + (size_t)(kt + 16 + br) * DH + bdq);
        }

#pragma unroll
        for (int kk = 0; kk < 16; kk++) {
            float a[8], bb[4];
#pragma unroll
            for (int i = 0; i < 8; i++) a[i] = As[kk][ty * 8 + i];
#pragma unroll
            for (int j = 0; j < 4; j++) bb[j] = Bs[kk][tx * 4 + j];
#pragma unroll
            for (int i = 0; i < 8; i++)
#pragma unroll
                for (int j = 0; j < 4; j++) acc[i][j] += a[i] * bb[j];
        }
    }

    const int irow = i0 + ty * 8;
    const int d0 = h * DH + tx * 4;
#pragma unroll
    for (int i = 0; i < 8; i++)
#pragma unroll
        for (int j = 0; j < 4; j++)
            g_ctx[((size_t)b * NN + irow + i) * DIMM + d0 + j] = acc[i][j];
}

// ---------------- host launcher ----------------
extern "C" void kernel_launch(void* const* d_in, const int* in_sizes, int n_in,
                              void* d_out, int out_size) {
    const float* x        = (const float*)d_in[0];
    const float* Wq       = (const float*)d_in[1];
    const float* Wk       = (const float*)d_in[2];
    const float* Wv       = (const float*)d_in[3];
    const float* pre_proj = (const float*)d_in[4];
    const float* post_proj= (const float*)d_in[5];
    const float* mem_k    = (const float*)d_in[6];
    const float* mem_v    = (const float*)d_in[7];
    const float* Wout     = (const float*)d_in[8];
    const float* bout     = (const float*)d_in[9];
    float* out = (float*)d_out;
    (void)in_sizes; (void)n_in; (void)out_size;

    const int topk_smem = (HH * JROW + HH * 256) * 4;  // 86,080 bytes
    cudaFuncSetAttribute(topk_kernel, cudaFuncAttributeMaxDynamicSharedMemorySize, topk_smem);
    cudaFuncSetAttribute(dots_gemm, cudaFuncAttributeMaxDynamicSharedMemorySize, DOTS_SMEM);

    fill_mem_kernel<<<64, 1024>>>(mem_k, mem_v);

    qkv_gemm<<<dim3(24, 32), 256>>>(x, Wq, Wk, Wv);

    dots_gemm<<<dim3(17, 8, 64), 256, DOTS_SMEM>>>();

    topk_kernel<<<BB * NN, 512, topk_smem>>>(pre_proj, post_proj);

    av_gemm<<<dim3(1, 8, 64), 256>>>();

    out_gemm<<<dim3(8, 32), 256>>>(Wout, bout, out);
}

// round 15
// speedup vs baseline: 1.2864x; 1.0022x over previous
#include <cuda_runtime.h>
#include <math.h>
#include <stdint.h>

// ---------------- problem constants ----------------
#define BB 4
#define NN 1024
#define DIMM 1024
#define HH 16
#define DH 64
#define NUM_MEM 64
#define JJ (NN + NUM_MEM)   // 1088
#define TOPKK 64
#define SCALEF 0.125f
#define NEGMAX (-3.402823466e38f)
#define JROW 1089           // padded row stride in shared

// ---------------- device scratch (allocation-free) ----------------
__device__ float g_q  [(size_t)BB*HH*NN*DH];
__device__ float g_k  [(size_t)BB*HH*JJ*DH];
__device__ float g_v  [(size_t)BB*HH*JJ*DH];
__device__ float g_raw[(size_t)BB*HH*NN*JJ];   // raw dots -> (reused) post-mixed attn
__device__ float g_ctx[(size_t)BB*NN*DIMM];

// monotone fp32 -> uint32 key (order-preserving)
__device__ __forceinline__ unsigned fkey(float f) {
    unsigned u = __float_as_uint(f);
    return (u & 0x80000000u) ? ~u : (u | 0x80000000u);
}

// ---------------- kernel 1: broadcast memory K/V into the kv cache ----------------
__global__ void fill_mem_kernel(const float* __restrict__ mk, const float* __restrict__ mv) {
    int idx = blockIdx.x * blockDim.x + threadIdx.x;
    if (idx >= HH * NUM_MEM * DH) return;
    int h    = idx / (NUM_MEM * DH);
    int rest = idx % (NUM_MEM * DH);
    float kv = mk[idx], vv = mv[idx];
#pragma unroll
    for (int b = 0; b < BB; b++) {
        size_t o = ((size_t)(b * HH + h) * JJ) * DH + rest;
        g_k[o] = kv;
        g_v[o] = vv;
    }
}

#define LDS_PAD 132

// ---------------- kernel 2a: MERGED QKV projection GEMM ----------------
__global__ __launch_bounds__(256, 2)
void qkv_gemm(const float* __restrict__ x, const float* __restrict__ Wq,
              const float* __restrict__ Wk, const float* __restrict__ Wv) {
    constexpr int K = 1024;
    constexpr int BK = 16;

    const int bn3 = blockIdx.x * 128;          // 0..2944
    const int which = bn3 >> 10;               // 0=q, 1=k, 2=v
    const int bn = bn3 & 1023;                 // column within the selected matrix
    const float* Bw = (which == 0) ? Wq : (which == 1) ? Wk : Wv;
    const int bm = blockIdx.y * 128;

    __shared__ __align__(16) float As[2][BK][LDS_PAD];
    __shared__ __align__(16) float Bs[2][BK][LDS_PAD];

    const int tid = threadIdx.x;
    const int tx = tid & 15, ty = tid >> 4;
    const int lm = tid >> 2;
    const int lk = (tid & 3) << 2;

    const float* Ald = x + (size_t)(bm + lm) * K + lk;
    const float* Bld = Bw + (size_t)(bn + lm) * K + lk;
    const size_t half = (size_t)64 * K;

    float4 ra0 = *(const float4*)(Ald);
    float4 ra1 = *(const float4*)(Ald + half);
    float4 rb0 = *(const float4*)(Bld);
    float4 rb1 = *(const float4*)(Bld + half);

    float acc[8][8];
#pragma unroll
    for (int i = 0; i < 8; i++)
#pragma unroll
        for (int j = 0; j < 8; j++) acc[i][j] = 0.f;

    As[0][lk+0][lm] = ra0.x; As[0][lk+1][lm] = ra0.y; As[0][lk+2][lm] = ra0.z; As[0][lk+3][lm] = ra0.w;
    As[0][lk+0][lm+64] = ra1.x; As[0][lk+1][lm+64] = ra1.y; As[0][lk+2][lm+64] = ra1.z; As[0][lk+3][lm+64] = ra1.w;
    Bs[0][lk+0][lm] = rb0.x; Bs[0][lk+1][lm] = rb0.y; Bs[0][lk+2][lm] = rb0.z; Bs[0][lk+3][lm] = rb0.w;
    Bs[0][lk+0][lm+64] = rb1.x; Bs[0][lk+1][lm+64] = rb1.y; Bs[0][lk+2][lm+64] = rb1.z; Bs[0][lk+3][lm+64] = rb1.w;
    __syncthreads();

    int buf = 0;
    for (int t = 1; t < K / BK; t++) {
        const float* A2 = Ald + t * BK;
        const float* B2 = Bld + t * BK;
        ra0 = *(const float4*)(A2);
        ra1 = *(const float4*)(A2 + half);
        rb0 = *(const float4*)(B2);
        rb1 = *(const float4*)(B2 + half);

#pragma unroll
        for (int kk = 0; kk < BK; kk++) {
            float a[8], b[8];
            *(float4*)(a)     = *(const float4*)&As[buf][kk][ty * 8];
            *(float4*)(a + 4) = *(const float4*)&As[buf][kk][ty * 8 + 4];
            *(float4*)(b)     = *(const float4*)&Bs[buf][kk][tx * 8];
            *(float4*)(b + 4) = *(const float4*)&Bs[buf][kk][tx * 8 + 4];
#pragma unroll
            for (int i = 0; i < 8; i++)
#pragma unroll
                for (int j = 0; j < 8; j++) acc[i][j] += a[i] * b[j];
        }

        const int nb = buf ^ 1;
        As[nb][lk+0][lm] = ra0.x; As[nb][lk+1][lm] = ra0.y; As[nb][lk+2][lm] = ra0.z; As[nb][lk+3][lm] = ra0.w;
        As[nb][lk+0][lm+64] = ra1.x; As[nb][lk+1][lm+64] = ra1.y; As[nb][lk+2][lm+64] = ra1.z; As[nb][lk+3][lm+64] = ra1.w;
        Bs[nb][lk+0][lm] = rb0.x; Bs[nb][lk+1][lm] = rb0.y; Bs[nb][lk+2][lm] = rb0.z; Bs[nb][lk+3][lm] = rb0.w;
        Bs[nb][lk+0][lm+64] = rb1.x; Bs[nb][lk+1][lm+64] = rb1.y; Bs[nb][lk+2][lm+64] = rb1.z; Bs[nb][lk+3][lm+64] = rb1.w;
        __syncthreads();
        buf = nb;
    }

#pragma unroll
    for (int kk = 0; kk < BK; kk++) {
        float a[8], b[8];
        *(float4*)(a)     = *(const float4*)&As[buf][kk][ty * 8];
        *(float4*)(a + 4) = *(const float4*)&As[buf][kk][ty * 8 + 4];
        *(float4*)(b)     = *(const float4*)&Bs[buf][kk][tx * 8];
        *(float4*)(b + 4) = *(const float4*)&Bs[buf][kk][tx * 8 + 4];
#pragma unroll
        for (int i = 0; i < 8; i++)
#pragma unroll
            for (int j = 0; j < 8; j++) acc[i][j] += a[i] * b[j];
    }

#pragma unroll
    for (int i = 0; i < 8; i++) {
        int m = bm + ty * 8 + i;
        int b = m >> 10, pos = m & 1023;
#pragma unroll
        for (int j = 0; j < 8; j++) {
            int n = bn + tx * 8 + j;
            int h = n >> 6, d = n & 63;
            if (which == 0) {
                g_q[((size_t)(b * HH + h) * NN + pos) * DH + d] = acc[i][j];
            } else if (which == 1) {
                g_k[((size_t)(b * HH + h) * JJ + NUM_MEM + pos) * DH + d] = acc[i][j];
            } else {
                g_v[((size_t)(b * HH + h) * JJ + NUM_MEM + pos) * DH + d] = acc[i][j];
            }
        }
    }
}

// ---------------- kernel 2b: output projection GEMM (A = g_ctx, C = out + bias) ----------
__global__ __launch_bounds__(256, 2)
void out_gemm(const float* __restrict__ Bw, const float* __restrict__ bias, float* __restrict__ C) {
    constexpr int K = 1024;
    constexpr int BK = 16;
    const float* Ap = (const float*)g_ctx;

    const int bm = blockIdx.y * 128;
    const int bn = blockIdx.x * 128;

    __shared__ __align__(16) float As[2][BK][LDS_PAD];
    __shared__ __align__(16) float Bs[2][BK][LDS_PAD];

    const int tid = threadIdx.x;
    const int tx = tid & 15, ty = tid >> 4;
    const int lm = tid >> 2;
    const int lk = (tid & 3) << 2;

    const float* Ald = Ap + (size_t)(bm + lm) * K + lk;
    const float* Bld = Bw + (size_t)(bn + lm) * K + lk;
    const size_t half = (size_t)64 * K;

    float4 ra0 = *(const float4*)(Ald);
    float4 ra1 = *(const float4*)(Ald + half);
    float4 rb0 = *(const float4*)(Bld);
    float4 rb1 = *(const float4*)(Bld + half);

    float acc[8][8];
#pragma unroll
    for (int i = 0; i < 8; i++)
#pragma unroll
        for (int j = 0; j < 8; j++) acc[i][j] = 0.f;

    As[0][lk+0][lm] = ra0.x; As[0][lk+1][lm] = ra0.y; As[0][lk+2][lm] = ra0.z; As[0][lk+3][lm] = ra0.w;
    As[0][lk+0][lm+64] = ra1.x; As[0][lk+1][lm+64] = ra1.y; As[0][lk+2][lm+64] = ra1.z; As[0][lk+3][lm+64] = ra1.w;
    Bs[0][lk+0][lm] = rb0.x; Bs[0][lk+1][lm] = rb0.y; Bs[0][lk+2][lm] = rb0.z; Bs[0][lk+3][lm] = rb0.w;
    Bs[0][lk+0][lm+64] = rb1.x; Bs[0][lk+1][lm+64] = rb1.y; Bs[0][lk+2][lm+64] = rb1.z; Bs[0][lk+3][lm+64] = rb1.w;
    __syncthreads();

    int buf = 0;
    for (int t = 1; t < K / BK; t++) {
        const float* A2 = Ald + t * BK;
        const float* B2 = Bld + t * BK;
        ra0 = *(const float4*)(A2);
        ra1 = *(const float4*)(A2 + half);
        rb0 = *(const float4*)(B2);
        rb1 = *(const float4*)(B2 + half);

#pragma unroll
        for (int kk = 0; kk < BK; kk++) {
            float a[8], b[8];
            *(float4*)(a)     = *(const float4*)&As[buf][kk][ty * 8];
            *(float4*)(a + 4) = *(const float4*)&As[buf][kk][ty * 8 + 4];
            *(float4*)(b)     = *(const float4*)&Bs[buf][kk][tx * 8];
            *(float4*)(b + 4) = *(const float4*)&Bs[buf][kk][tx * 8 + 4];
#pragma unroll
            for (int i = 0; i < 8; i++)
#pragma unroll
                for (int j = 0; j < 8; j++) acc[i][j] += a[i] * b[j];
        }

        const int nb = buf ^ 1;
        As[nb][lk+0][lm] = ra0.x; As[nb][lk+1][lm] = ra0.y; As[nb][lk+2][lm] = ra0.z; As[nb][lk+3][lm] = ra0.w;
        As[nb][lk+0][lm+64] = ra1.x; As[nb][lk+1][lm+64] = ra1.y; As[nb][lk+2][lm+64] = ra1.z; As[nb][lk+3][lm+64] = ra1.w;
        Bs[nb][lk+0][lm] = rb0.x; Bs[nb][lk+1][lm] = rb0.y; Bs[nb][lk+2][lm] = rb0.z; Bs[nb][lk+3][lm] = rb0.w;
        Bs[nb][lk+0][lm+64] = rb1.x; Bs[nb][lk+1][lm+64] = rb1.y; Bs[nb][lk+2][lm+64] = rb1.z; Bs[nb][lk+3][lm+64] = rb1.w;
        __syncthreads();
        buf = nb;
    }

#pragma unroll
    for (int kk = 0; kk < BK; kk++) {
        float a[8], b[8];
        *(float4*)(a)     = *(const float4*)&As[buf][kk][ty * 8];
        *(float4*)(a + 4) = *(const float4*)&As[buf][kk][ty * 8 + 4];
        *(float4*)(b)     = *(const float4*)&Bs[buf][kk][tx * 8];
        *(float4*)(b + 4) = *(const float4*)&Bs[buf][kk][tx * 8 + 4];
#pragma unroll
        for (int i = 0; i < 8; i++)
#pragma unroll
            for (int j = 0; j < 8; j++) acc[i][j] += a[i] * b[j];
    }

#pragma unroll
    for (int i = 0; i < 8; i++) {
        int m = bm + ty * 8 + i;
#pragma unroll
        for (int j = 0; j < 8; j++) {
            int n = bn + tx * 8 + j;
            C[(size_t)m * 1024 + n] = acc[i][j] + bias[n];
        }
    }
}

// ---------------- kernel 3: raw dots = SCALE * Q @ K^T, 128x64 tiles (8x4/thread) -------
#define DOTS_SMEM ((64 * 132 + 64 * 68) * 4)   // 51200 bytes
__global__ __launch_bounds__(256)
void dots_gemm() {
    extern __shared__ float dsm[];
    float (*Qs)[132] = (float(*)[132])dsm;            // [d][i], 128 rows
    float (*Ks)[68]  = (float(*)[68])(dsm + 64 * 132); // [d][j]

    const int bh = blockIdx.z;
    const int i0 = blockIdx.y * 128;
    const int j0 = blockIdx.x * 64;
    if (j0 > i0 + 191) return;

    const float* Qp = g_q + ((size_t)bh * NN + i0) * DH;
    const float* Kp = g_k + ((size_t)bh * JJ + j0) * DH;

    const int tid = threadIdx.x;
    for (int f = tid; f < 2048; f += 256) {
        int r = f >> 4, dq = (f & 15) << 2;
        float4 q4 = *(const float4*)(Qp + (size_t)r * DH + dq);
        Qs[dq + 0][r] = q4.x; Qs[dq + 1][r] = q4.y; Qs[dq + 2][r] = q4.z; Qs[dq + 3][r] = q4.w;
    }
    for (int f = tid; f < 1024; f += 256) {
        int r = f >> 4, dq = (f & 15) << 2;
        float4 k4 = *(const float4*)(Kp + (size_t)r * DH + dq);
        Ks[dq + 0][r] = k4.x; Ks[dq + 1][r] = k4.y; Ks[dq + 2][r] = k4.z; Ks[dq + 3][r] = k4.w;
    }
    __syncthreads();

    const int tx = tid & 15, ty = tid >> 4;
    float acc[8][4];
#pragma unroll
    for (int i = 0; i < 8; i++)
#pragma unroll
        for (int j = 0; j < 4; j++) acc[i][j] = 0.f;

#pragma unroll 8
    for (int d = 0; d < 64; d++) {
        float a[8], b[4];
#pragma unroll
        for (int i = 0; i < 8; i++) a[i] = Qs[d][ty * 8 + i];
#pragma unroll
        for (int j = 0; j < 4; j++) b[j] = Ks[d][tx * 4 + j];
#pragma unroll
        for (int i = 0; i < 8; i++)
#pragma unroll
            for (int j = 0; j < 4; j++) acc[i][j] += a[i] * b[j];
    }

    size_t ob = ((size_t)bh * NN + i0 + ty * 8) * JJ + j0 + tx * 4;
#pragma unroll
    for (int i = 0; i < 8; i++)
#pragma unroll
        for (int j = 0; j < 4; j++)
            g_raw[ob + (size_t)i * JJ + j] = acc[i][j] * SCALEF;
}

// ---------------- kernel 5: FUSED pre-mix + top-k + softmax + post-mix ----------------
// Phase A stages 16x256 tiles of g_raw in the HIST region (dead during Phase A,
// identical 16 KB footprint; each radix pass re-zeroes it), mixes via s_pre, and
// writes mixed rows directly to shared — g_mix eliminated entirely.
__global__ __launch_bounds__(512, 2)
void topk_kernel(const float* __restrict__ pre_proj, const float* __restrict__ post_proj) {
    extern __shared__ float sm[];
    float* rows = sm;                                  // 16 * JROW floats
    unsigned* hist = (unsigned*)(sm + HH * JROW);      // 16 * 256 uints
    float* tile = (float*)hist;                        // Phase A staging (borrowed)
    __shared__ float s_pre[256];
    __shared__ float s_post[256];

    const int b = blockIdx.x >> 10;
    const int i = blockIdx.x & 1023;
    const int tid = threadIdx.x;
    const int w = tid >> 5, lane = tid & 31;
    if (tid < 256) { s_pre[tid] = pre_proj[tid]; s_post[tid] = post_proj[tid]; }
    __syncthreads();

    const int jlen = i + NUM_MEM + 1;
    const size_t rawbase = ((size_t)b * HH * NN + i) * JJ;
    const size_t hs = (size_t)NN * JJ;

    // ---- Phase A: smem-staged pre-mix, global g_raw -> shared rows ----
    for (int j0 = 0; j0 < jlen; j0 += 256) {
        const int n = min(256, jlen - j0);
        __syncthreads();
        for (int f = tid; f < HH * 256; f += 512) {
            int h = f >> 8, t = f & 255;
            if (t < n) tile[h * 256 + t] = g_raw[rawbase + (size_t)h * hs + j0 + t];
        }
        __syncthreads();
        if (tid < n) {
            float r[HH];
#pragma unroll
            for (int h = 0; h < HH; h++) r[h] = tile[h * 256 + tid];
#pragma unroll
            for (int kk = 0; kk < HH; kk++) {
                float s = 0.f;
#pragma unroll
                for (int h = 0; h < HH; h++) s += r[h] * s_pre[h * HH + kk];
                rows[kk * JROW + j0 + tid] = s;
            }
        }
    }
    __syncthreads();

    // ---- Phase B: warp w owns mixed head w ----
    float* srow = rows + w * JROW;
    unsigned* myh = hist + w * 256;

    float m = NEGMAX;
    for (int j = lane; j < jlen; j += 32) m = fmaxf(m, srow[j]);
#pragma unroll
    for (int o = 16; o; o >>= 1) m = fmaxf(m, __shfl_xor_sync(0xffffffffu, m, o));

    unsigned prefix = 0;
    int r = TOPKK;
#pragma unroll
    for (int shift = 24; shift >= 0; shift -= 8) {
        for (int t = lane; t < 256; t += 32) myh[t] = 0;
        __syncwarp();
        unsigned pm = (shift == 24) ? 0u : (0xFFFFFFFFu << (shift + 8));
        for (int j = lane; j < jlen; j += 32) {
            unsigned kx = fkey(srow[j]);
            if ((kx & pm) == prefix) atomicAdd(&myh[(kx >> shift) & 255u], 1u);
        }
        __syncwarp();
        unsigned tot = 0;
#pragma unroll
        for (int t = 0; t < 8; t++) tot += myh[lane * 8 + t];
        unsigned s = tot;
#pragma unroll
        for (int o = 1; o < 32; o <<= 1) {
            unsigned tt = __shfl_down_sync(0xffffffffu, s, o);
            if (lane + o < 32) s += tt;
        }
        unsigned s_strict = s - tot;
        bool sel = ((unsigned)r > s_strict) && ((unsigned)r <= s);
        unsigned bal = __ballot_sync(0xffffffffu, sel);
        int sl = __ffs(bal) - 1;
        unsigned pick = 0; int newr = r;
        if (sel) {
            int rr = r - (int)s_strict;
#pragma unroll
            for (int t = 7; t >= 0; t--) {
                unsigned c = myh[lane * 8 + t];
                if (rr <= (int)c) { pick = (unsigned)(lane * 8 + t); newr = rr; break; }
                rr -= (int)c;
            }
        }
        pick = __shfl_sync(0xffffffffu, pick, sl);
        r    = __shfl_sync(0xffffffffu, newr, sl);
        prefix |= pick << shift;
    }

    float sum = 0.f;
    for (int j = lane; j < JJ; j += 32) {
        float e = 0.f;
        if (j < jlen) {
            float v = srow[j];
            if (fkey(v) >= prefix) e = expf(v - m);
        }
        srow[j] = e;
        sum += e;
    }
#pragma unroll
    for (int o = 16; o; o >>= 1) sum += __shfl_xor_sync(0xffffffffu, sum, o);
    float inv = 1.0f / sum;
    for (int j = lane; j < JJ; j += 32) srow[j] *= inv;

    __syncthreads();

    // ---- Phase C: post-mix. av_gemm (128-row tiles) reads k < min(JJ, (i/128)*128+192) ----
    const int wlim = min(JJ, (i & ~127) + 192);
    const size_t ob = ((size_t)(b * HH) * NN + i) * JJ;
    for (int j = tid; j < wlim; j += 512) {
        float a[HH];
#pragma unroll
        for (int hh = 0; hh < HH; hh++) a[hh] = rows[hh * JROW + j];
#pragma unroll
        for (int kk = 0; kk < HH; kk++) {
            float sacc = 0.f;
#pragma unroll
            for (int hh = 0; hh < HH; hh++) sacc += a[hh] * s_post[hh * 16 + kk];
            g_raw[ob + (size_t)kk * hs + j] = sacc;
        }
    }
}

// ---------------- kernel 6: context = attn2 @ V, 128x64 tiles (8x4/thread), pipelined ----
__global__ __launch_bounds__(256)
void av_gemm() {
    const int bh = blockIdx.z;
    const int b = bh >> 4, h = bh & 15;
    const int i0 = blockIdx.y * 128;

    const float* Ap = g_raw + ((size_t)bh * NN + i0) * JJ;
    const float* Vp = g_v + (size_t)bh * JJ * DH;
    const int kmax = min(JJ, i0 + 192);

    __shared__ float As[16][132];  // [k][i], 128 rows
    __shared__ float Bs[16][68];   // [k][d]

    const int tid = threadIdx.x;
    const int tx = tid & 15, ty = tid >> 4;
    const int ar = tid >> 1, ak8 = (tid & 1) << 3;
    const int br = tid >> 4, bdq = (tid & 15) << 2;

    float acc[8][4];
#pragma unroll
    for (int i = 0; i < 8; i++)
#pragma unroll
        for (int j = 0; j < 4; j++) acc[i][j] = 0.f;

    float4 a4a = *(const float4*)(Ap + (size_t)ar * JJ + ak8);
    float4 a4b = *(const float4*)(Ap + (size_t)ar * JJ + ak8 + 4);
    float4 b4  = *(const float4*)(Vp + (size_t)br * DH + bdq);

    for (int kt = 0; kt < kmax; kt += 16) {
        __syncthreads();
        As[ak8 + 0][ar] = a4a.x; As[ak8 + 1][ar] = a4a.y; As[ak8 + 2][ar] = a4a.z; As[ak8 + 3][ar] = a4a.w;
        As[ak8 + 4][ar] = a4b.x; As[ak8 + 5][ar] = a4b.y; As[ak8 + 6][ar] = a4b.z; As[ak8 + 7][ar] = a4b.w;
        *(float4*)&Bs[br][bdq] = b4;
        __syncthreads();

        if (kt + 16 < kmax) {
            a4a = *(const float4*)(Ap + (size_t)ar * JJ + kt + 16 + ak8);
            a4b = *(const float4*)(Ap + (size_t)ar * JJ + kt + 16 + ak8 + 4);
            b4  = *(const float4*)(Vp + (size_t)(kt + 16 + br) * DH + bdq);
        }

#pragma unroll
        for (int kk = 0; kk < 16; kk++) {
            float a[8], bb[4];
#pragma unroll
            for (int i = 0; i < 8; i++) a[i] = As[kk][ty * 8 + i];
#pragma unroll
            for (int j = 0; j < 4; j++) bb[j] = Bs[kk][tx * 4 + j];
#pragma unroll
            for (int i = 0; i < 8; i++)
#pragma unroll
                for (int j = 0; j < 4; j++) acc[i][j] += a[i] * bb[j];
        }
    }

    const int irow = i0 + ty * 8;
    const int d0 = h * DH + tx * 4;
#pragma unroll
    for (int i = 0; i < 8; i++)
#pragma unroll
        for (int j = 0; j < 4; j++)
            g_ctx[((size_t)b * NN + irow + i) * DIMM + d0 + j] = acc[i][j];
}

// ---------------- host launcher ----------------
extern "C" void kernel_launch(void* const* d_in, const int* in_sizes, int n_in,
                              void* d_out, int out_size) {
    const float* x        = (const float*)d_in[0];
    const float* Wq       = (const float*)d_in[1];
    const float* Wk       = (const float*)d_in[2];
    const float* Wv       = (const float*)d_in[3];
    const float* pre_proj = (const float*)d_in[4];
    const float* post_proj= (const float*)d_in[5];
    const float* mem_k    = (const float*)d_in[6];
    const float* mem_v    = (const float*)d_in[7];
    const float* Wout     = (const float*)d_in[8];
    const float* bout     = (const float*)d_in[9];
    float* out = (float*)d_out;
    (void)in_sizes; (void)n_in; (void)out_size;

    const int topk_smem = (HH * JROW + HH * 256) * 4;  // 86,080 bytes
    cudaFuncSetAttribute(topk_kernel, cudaFuncAttributeMaxDynamicSharedMemorySize, topk_smem);
    cudaFuncSetAttribute(dots_gemm, cudaFuncAttributeMaxDynamicSharedMemorySize, DOTS_SMEM);

    fill_mem_kernel<<<64, 1024>>>(mem_k, mem_v);

    qkv_gemm<<<dim3(24, 32), 256>>>(x, Wq, Wk, Wv);

    dots_gemm<<<dim3(17, 8, 64), 256, DOTS_SMEM>>>();

    topk_kernel<<<BB * NN, 512, topk_smem>>>(pre_proj, post_proj);

    av_gemm<<<dim3(1, 8, 64), 256>>>();

    out_gemm<<<dim3(8, 32), 256>>>(Wout, bout, out);
}